// round 7
// baseline (speedup 1.0000x reference)
#include <cuda_runtime.h>
#include <cuda_fp16.h>

#define NN    100000
#define FEAT  128
#define CLS   40
#define EMAX  1600000

// ---- scratch (static device globals; no allocation allowed) ----
__device__ int    g_degi[NN];                 // zero at load; re-zeroed by spmm128
__device__ float  g_dinv[NN];
__device__ __half g_Hh[(size_t)NN * FEAT];    // pre-scaled fp16 messages h*dinv
__device__ __half g_AGG[(size_t)NN * FEAT];   // fp16 aggregation buffer
__device__ __half g_H2h[(size_t)NN * CLS];    // layer-2 pre-scaled fp16 messages
__device__ int    g_rowptr[NN];               // segment start per node (unordered)
__device__ int    g_cursor[NN];               // post-fill: segment end per node
__device__ int    g_total;

// ---- mma helpers ----
__device__ __forceinline__ unsigned sm_u32(const void* p) {
    return (unsigned)__cvta_generic_to_shared(p);
}
__device__ __forceinline__ void ldm_x4(unsigned* r, unsigned a) {
    asm volatile("ldmatrix.sync.aligned.m8n8.x4.shared.b16 {%0,%1,%2,%3}, [%4];"
                 : "=r"(r[0]), "=r"(r[1]), "=r"(r[2]), "=r"(r[3]) : "r"(a));
}
__device__ __forceinline__ void ldm_x4t(unsigned* r, unsigned a) {
    asm volatile("ldmatrix.sync.aligned.m8n8.x4.trans.shared.b16 {%0,%1,%2,%3}, [%4];"
                 : "=r"(r[0]), "=r"(r[1]), "=r"(r[2]), "=r"(r[3]) : "r"(a));
}
__device__ __forceinline__ void mma16816(float* d, const unsigned* a,
                                         const unsigned* b) {
    asm volatile(
        "mma.sync.aligned.m16n8k16.row.col.f32.f16.f16.f32 "
        "{%0,%1,%2,%3},{%4,%5,%6,%7},{%8,%9},{%0,%1,%2,%3};"
        : "+f"(d[0]), "+f"(d[1]), "+f"(d[2]), "+f"(d[3])
        : "r"(a[0]), "r"(a[1]), "r"(a[2]), "r"(a[3]), "r"(b[0]), "r"(b[1]));
}

__device__ __forceinline__ bool ei_is64(const void* ei, int n) {
    const unsigned long long* p = (const unsigned long long*)ei;
    return p[0] < (unsigned long long)n && p[1] < (unsigned long long)n;
}

// ------------------------------------------------------------------
// CSR build (unordered segments): count -> offset -> fill
// ------------------------------------------------------------------
__global__ void k_count(const void* ei, int n, int E) {
    if (blockIdx.x == 0 && threadIdx.x == 0) g_total = 0;
    int e = blockIdx.x * blockDim.x + threadIdx.x;
    if (e >= E) return;
    bool is64 = ei_is64(ei, n);
    int dst = is64 ? (int)((const long long*)ei)[E + e]
                   : ((const int*)ei)[E + e];
    atomicAdd(&g_degi[dst], 1);
}

// per-256-node block: local scan + atomic base; also writes dinv
__global__ void k_offset(int n) {
    __shared__ int wsum[8];
    __shared__ int base;
    int t = threadIdx.x;
    int i = blockIdx.x * 256 + t;
    int lane = t & 31, warp = t >> 5;
    int deg = (i < n) ? g_degi[i] : 0;
    if (i < n) g_dinv[i] = rsqrtf((float)deg + 1.f);
    // warp inclusive scan
    int v = deg;
#pragma unroll
    for (int off = 1; off < 32; off <<= 1) {
        int x = __shfl_up_sync(0xffffffffu, v, off);
        if (lane >= off) v += x;
    }
    if (lane == 31) wsum[warp] = v;
    __syncthreads();
    if (warp == 0 && lane < 8) {
        int s = wsum[lane];
#pragma unroll
        for (int off = 1; off < 8; off <<= 1) {
            int x = __shfl_up_sync(0xffu, s, off);
            if (lane >= off) s += x;
        }
        wsum[lane] = s;
    }
    __syncthreads();
    if (t == 0) base = atomicAdd(&g_total, wsum[7]);
    __syncthreads();
    if (i < n) {
        int incl = v + (warp > 0 ? wsum[warp - 1] : 0);
        int r = base + incl - deg;
        g_rowptr[i] = r;
        g_cursor[i] = r;
    }
}

__global__ void k_fill(const void* ei, int n, int E) {
    int e = blockIdx.x * blockDim.x + threadIdx.x;
    if (e >= E) return;
    bool is64 = ei_is64(ei, n);
    int s, d;
    if (is64) {
        const long long* p = (const long long*)ei;
        s = (int)p[e]; d = (int)p[E + e];
    } else {
        const int* p = (const int*)ei;
        s = p[e]; d = p[E + e];
    }
    int pos = atomicAdd(&g_cursor[d], 1);
    // g_csr in a separate array below
    extern __device__ int g_csr[];
    g_csr[pos] = s;
}
__device__ int g_csr[EMAX];

// ------------------------------------------------------------------
// Tensor-core GEMM (K=128, Nout=128): h = act(A) @ W  (fp16 in, fp32 acc)
//   Hh  = half(h * dinv)        (pre-scaled message)
//   AGG = half(h * dinv^2 + b)  (self-loop + bias)
// BM=128, BN=128, BK=64, 8 warps (4x2), warp tile 32x64, mma 16x8x16
// HIN: A is fp16 (g_AGG); else fp32 (input x)
// ------------------------------------------------------------------
template <bool RELU, bool HIN>
__global__ __launch_bounds__(256, 2)
void k_gemm128h(const void* __restrict__ Ain, const float* __restrict__ W,
                const float* __restrict__ b, __half* __restrict__ Hh,
                __half* __restrict__ AGG, int n) {
    __shared__ __half As[128][72];   // [m][k], pad 8 -> conflict-free ldmatrix
    __shared__ __half Ws[64][136];   // [k][n], pad 8
    const int tid  = threadIdx.x;
    const int lane = tid & 31;
    const int warp = tid >> 5;
    const int wm   = warp & 3;
    const int wn   = warp >> 2;
    const int row0 = blockIdx.x * 128;

    float acc[2][8][4];
#pragma unroll
    for (int mi = 0; mi < 2; mi++)
#pragma unroll
        for (int ni = 0; ni < 8; ni++)
#pragma unroll
            for (int q = 0; q < 4; q++) acc[mi][ni][q] = 0.f;

    const int ar = tid >> 1, ac = (tid & 1) * 32;
    const int wr = tid >> 2, wc = (tid & 3) * 32;
    const __half2 z2 = __float2half2_rn(0.f);

#pragma unroll
    for (int kb = 0; kb < 2; kb++) {
        if (kb) __syncthreads();
        // A tile -> smem
        {
            int gr = row0 + ar;
            if (HIN) {
                const __half* Arow = (const __half*)Ain + (size_t)gr * 128 + kb * 64 + ac;
#pragma unroll
                for (int u = 0; u < 4; u++) {
                    uint4 raw = make_uint4(0, 0, 0, 0);
                    if (gr < n) raw = *(const uint4*)(Arow + u * 8);
                    if (RELU) {
                        __half2* hp = (__half2*)&raw;
#pragma unroll
                        for (int q = 0; q < 4; q++) hp[q] = __hmax2(hp[q], z2);
                    }
                    *(uint4*)&As[ar][ac + u * 8] = raw;
                }
            } else {
                const float* Arow = (const float*)Ain + (size_t)gr * 128 + kb * 64 + ac;
#pragma unroll
                for (int u = 0; u < 4; u++) {
                    float4 f0 = make_float4(0.f, 0.f, 0.f, 0.f), f1 = f0;
                    if (gr < n) {
                        f0 = *(const float4*)(Arow + u * 8);
                        f1 = *(const float4*)(Arow + u * 8 + 4);
                    }
                    if (RELU) {
                        f0.x = fmaxf(f0.x, 0.f); f0.y = fmaxf(f0.y, 0.f);
                        f0.z = fmaxf(f0.z, 0.f); f0.w = fmaxf(f0.w, 0.f);
                        f1.x = fmaxf(f1.x, 0.f); f1.y = fmaxf(f1.y, 0.f);
                        f1.z = fmaxf(f1.z, 0.f); f1.w = fmaxf(f1.w, 0.f);
                    }
                    __half2 hh[4];
                    hh[0] = __floats2half2_rn(f0.x, f0.y);
                    hh[1] = __floats2half2_rn(f0.z, f0.w);
                    hh[2] = __floats2half2_rn(f1.x, f1.y);
                    hh[3] = __floats2half2_rn(f1.z, f1.w);
                    *(uint4*)&As[ar][ac + u * 8] = *(uint4*)hh;
                }
            }
        }
        // W tile (fp32 -> fp16)
        {
            const float* Wrow = W + (size_t)(kb * 64 + wr) * 128 + wc;
#pragma unroll
            for (int u = 0; u < 4; u++) {
                float4 f0 = *(const float4*)(Wrow + u * 8);
                float4 f1 = *(const float4*)(Wrow + u * 8 + 4);
                __half2 hh[4];
                hh[0] = __floats2half2_rn(f0.x, f0.y);
                hh[1] = __floats2half2_rn(f0.z, f0.w);
                hh[2] = __floats2half2_rn(f1.x, f1.y);
                hh[3] = __floats2half2_rn(f1.z, f1.w);
                *(uint4*)&Ws[wr][wc + u * 8] = *(uint4*)hh;
            }
        }
        __syncthreads();

#pragma unroll
        for (int kk = 0; kk < 4; kk++) {
            unsigned af[2][4];
#pragma unroll
            for (int mi = 0; mi < 2; mi++) {
                int r = wm * 32 + mi * 16 + (lane & 15);
                int kh = kk * 16 + (lane >> 4) * 8;
                ldm_x4(af[mi], sm_u32(&As[r][kh]));
            }
            unsigned bf[8][2];
#pragma unroll
            for (int nt = 0; nt < 4; nt++) {
                int g = lane >> 3, r = lane & 7;
                int krow = kk * 16 + (g & 1) * 8 + r;
                int ncol = wn * 64 + nt * 16 + (g >> 1) * 8;
                unsigned t[4];
                ldm_x4t(t, sm_u32(&Ws[krow][ncol]));
                bf[nt * 2 + 0][0] = t[0]; bf[nt * 2 + 0][1] = t[1];
                bf[nt * 2 + 1][0] = t[2]; bf[nt * 2 + 1][1] = t[3];
            }
#pragma unroll
            for (int mi = 0; mi < 2; mi++)
#pragma unroll
                for (int ni = 0; ni < 8; ni++)
                    mma16816(acc[mi][ni], af[mi], bf[ni]);
        }
    }

    const int r1 = lane >> 2;
    const int c2 = (lane & 3) * 2;
    float2 bias2[8];
#pragma unroll
    for (int ni = 0; ni < 8; ni++)
        bias2[ni] = *(const float2*)(b + wn * 64 + ni * 8 + c2);
#pragma unroll
    for (int mi = 0; mi < 2; mi++) {
        int gr0 = row0 + wm * 32 + mi * 16 + r1;
        int gr1 = gr0 + 8;
        float d0 = (gr0 < n) ? g_dinv[gr0] : 0.f;
        float d1 = (gr1 < n) ? g_dinv[gr1] : 0.f;
        float dd0 = d0 * d0, dd1 = d1 * d1;
#pragma unroll
        for (int ni = 0; ni < 8; ni++) {
            int col = wn * 64 + ni * 8 + c2;
            float c0 = acc[mi][ni][0], c1 = acc[mi][ni][1];
            float c3 = acc[mi][ni][2], c4 = acc[mi][ni][3];
            if (gr0 < n) {
                __half2 h = __floats2half2_rn(c0 * d0, c1 * d0);
                *(unsigned*)(Hh + (size_t)gr0 * 128 + col) = *(unsigned*)&h;
                __half2 g = __floats2half2_rn(c0 * dd0 + bias2[ni].x,
                                              c1 * dd0 + bias2[ni].y);
                *(unsigned*)(AGG + (size_t)gr0 * 128 + col) = *(unsigned*)&g;
            }
            if (gr1 < n) {
                __half2 h = __floats2half2_rn(c3 * d1, c4 * d1);
                *(unsigned*)(Hh + (size_t)gr1 * 128 + col) = *(unsigned*)&h;
                __half2 g = __floats2half2_rn(c3 * dd1 + bias2[ni].x,
                                              c4 * dd1 + bias2[ni].y);
                *(unsigned*)(AGG + (size_t)gr1 * 128 + col) = *(unsigned*)&g;
            }
        }
    }
}

// ------------------------------------------------------------------
// Tensor-core GEMM (K=128, Nout=40 padded to 64), fp16 A (g_AGG):
//   h2  = relu(A) @ W2
//   H2h = half(h2 * dinv) ; OUT = h2 * dinv^2 + b2 (fp32)
// ------------------------------------------------------------------
__global__ __launch_bounds__(256, 2)
void k_gemm40h(const __half* __restrict__ A, const float* __restrict__ W,
               const float* __restrict__ b, __half* __restrict__ H2h,
               float* __restrict__ OUT, int n) {
    __shared__ __half As[128][72];
    __shared__ __half Ws[64][72];    // [k][n] 64 cols (40 real, rest 0)
    const int tid  = threadIdx.x;
    const int lane = tid & 31;
    const int warp = tid >> 5;
    const int wm   = warp & 3;
    const int wn   = warp >> 2;
    const int row0 = blockIdx.x * 128;
    const __half2 z2 = __float2half2_rn(0.f);

    float acc[2][4][4];
#pragma unroll
    for (int mi = 0; mi < 2; mi++)
#pragma unroll
        for (int ni = 0; ni < 4; ni++)
#pragma unroll
            for (int q = 0; q < 4; q++) acc[mi][ni][q] = 0.f;

    const int ar = tid >> 1, ac = (tid & 1) * 32;

#pragma unroll
    for (int kb = 0; kb < 2; kb++) {
        if (kb) __syncthreads();
        {
            int gr = row0 + ar;
            const __half* Arow = A + (size_t)gr * 128 + kb * 64 + ac;
#pragma unroll
            for (int u = 0; u < 4; u++) {
                uint4 raw = make_uint4(0, 0, 0, 0);
                if (gr < n) raw = *(const uint4*)(Arow + u * 8);
                __half2* hp = (__half2*)&raw;
#pragma unroll
                for (int q = 0; q < 4; q++) hp[q] = __hmax2(hp[q], z2);
                *(uint4*)&As[ar][ac + u * 8] = raw;
            }
        }
        for (int idx = tid; idx < 64 * 64; idx += 256) {
            int k = idx >> 6, c = idx & 63;
            float v = (c < 40) ? W[(size_t)(kb * 64 + k) * 40 + c] : 0.f;
            Ws[k][c] = __float2half_rn(v);
        }
        __syncthreads();

#pragma unroll
        for (int kk = 0; kk < 4; kk++) {
            unsigned af[2][4];
#pragma unroll
            for (int mi = 0; mi < 2; mi++) {
                int r = wm * 32 + mi * 16 + (lane & 15);
                int kh = kk * 16 + (lane >> 4) * 8;
                ldm_x4(af[mi], sm_u32(&As[r][kh]));
            }
            unsigned bf[4][2];
#pragma unroll
            for (int nt = 0; nt < 2; nt++) {
                int g = lane >> 3, r = lane & 7;
                int krow = kk * 16 + (g & 1) * 8 + r;
                int ncol = wn * 32 + nt * 16 + (g >> 1) * 8;
                unsigned t[4];
                ldm_x4t(t, sm_u32(&Ws[krow][ncol]));
                bf[nt * 2 + 0][0] = t[0]; bf[nt * 2 + 0][1] = t[1];
                bf[nt * 2 + 1][0] = t[2]; bf[nt * 2 + 1][1] = t[3];
            }
#pragma unroll
            for (int mi = 0; mi < 2; mi++)
#pragma unroll
                for (int ni = 0; ni < 4; ni++)
                    mma16816(acc[mi][ni], af[mi], bf[ni]);
        }
    }

    const int r1 = lane >> 2;
    const int c2 = (lane & 3) * 2;
#pragma unroll
    for (int mi = 0; mi < 2; mi++) {
        int gr0 = row0 + wm * 32 + mi * 16 + r1;
        int gr1 = gr0 + 8;
        float d0 = (gr0 < n) ? g_dinv[gr0] : 0.f;
        float d1 = (gr1 < n) ? g_dinv[gr1] : 0.f;
        float dd0 = d0 * d0, dd1 = d1 * d1;
#pragma unroll
        for (int ni = 0; ni < 4; ni++) {
            int col = wn * 32 + ni * 8 + c2;
            if (col >= 40) continue;
            float bx = b[col], by = b[col + 1];
            float c0 = acc[mi][ni][0], c1 = acc[mi][ni][1];
            float c3 = acc[mi][ni][2], c4 = acc[mi][ni][3];
            if (gr0 < n) {
                __half2 h = __floats2half2_rn(c0 * d0, c1 * d0);
                *(unsigned*)(H2h + (size_t)gr0 * 40 + col) = *(unsigned*)&h;
                *(float2*)(OUT + (size_t)gr0 * 40 + col) =
                    make_float2(c0 * dd0 + bx, c1 * dd0 + by);
            }
            if (gr1 < n) {
                __half2 h = __floats2half2_rn(c3 * d1, c4 * d1);
                *(unsigned*)(H2h + (size_t)gr1 * 40 + col) = *(unsigned*)&h;
                *(float2*)(OUT + (size_t)gr1 * 40 + col) =
                    make_float2(c3 * dd1 + bx, c4 * dd1 + by);
            }
        }
    }
}

// ------------------------------------------------------------------
// SpMM aggregation (fp16 messages, fp16 AGG):
//   AGG[d] += dinv[d] * sum_{s in seg d} Hh[s]
// one warp per dst node; also re-zeroes g_degi for the next call
// ------------------------------------------------------------------
__global__ __launch_bounds__(256)
void k_spmm128(const __half* __restrict__ hh, __half* __restrict__ agg, int n) {
    int w = (blockIdx.x * blockDim.x + threadIdx.x) >> 5;
    if (w >= n) return;
    int lane = threadIdx.x & 31;
    if (lane == 0) g_degi[w] = 0;
    int beg = g_rowptr[w];
    int end = g_cursor[w];
    float dd = g_dinv[w];
    float4 acc = make_float4(0.f, 0.f, 0.f, 0.f);

    int idx = beg;
    for (; idx + 4 <= end; idx += 4) {
        int s0 = g_csr[idx + 0], s1 = g_csr[idx + 1];
        int s2 = g_csr[idx + 2], s3 = g_csr[idx + 3];
        uint2 u0 = *(const uint2*)(hh + (size_t)s0 * 128 + lane * 4);
        uint2 u1 = *(const uint2*)(hh + (size_t)s1 * 128 + lane * 4);
        uint2 u2 = *(const uint2*)(hh + (size_t)s2 * 128 + lane * 4);
        uint2 u3 = *(const uint2*)(hh + (size_t)s3 * 128 + lane * 4);
#pragma unroll
        for (int q = 0; q < 4; q++) {
            uint2 u = (q == 0) ? u0 : (q == 1) ? u1 : (q == 2) ? u2 : u3;
            float2 f0 = __half22float2(*(const __half2*)&u.x);
            float2 f1 = __half22float2(*(const __half2*)&u.y);
            acc.x += f0.x; acc.y += f0.y; acc.z += f1.x; acc.w += f1.y;
        }
    }
    for (; idx < end; ++idx) {
        int s = g_csr[idx];
        uint2 u = *(const uint2*)(hh + (size_t)s * 128 + lane * 4);
        float2 f0 = __half22float2(*(const __half2*)&u.x);
        float2 f1 = __half22float2(*(const __half2*)&u.y);
        acc.x += f0.x; acc.y += f0.y; acc.z += f1.x; acc.w += f1.y;
    }
    __half* o = agg + (size_t)w * 128 + lane * 4;
    uint2 cu = *(uint2*)o;
    float2 a0 = __half22float2(*(const __half2*)&cu.x);
    float2 a1 = __half22float2(*(const __half2*)&cu.y);
    a0.x += dd * acc.x; a0.y += dd * acc.y;
    a1.x += dd * acc.z; a1.y += dd * acc.w;
    __half2 r0 = __floats2half2_rn(a0.x, a0.y);
    __half2 r1 = __floats2half2_rn(a1.x, a1.y);
    cu.x = *(unsigned*)&r0; cu.y = *(unsigned*)&r1;
    *(uint2*)o = cu;
}

// layer-2 spmm on fp16 pre-scaled messages (20 lanes x 2 cols), fp32 out
__global__ __launch_bounds__(256)
void k_spmm40h(const __half* __restrict__ hh, float* __restrict__ out, int n) {
    int w = (blockIdx.x * blockDim.x + threadIdx.x) >> 5;
    if (w >= n) return;
    int lane = threadIdx.x & 31;
    if (lane >= 20) return;
    int beg = g_rowptr[w];
    int end = g_cursor[w];
    float dd = g_dinv[w];
    float2 acc = make_float2(0.f, 0.f);

    int idx = beg;
    for (; idx + 4 <= end; idx += 4) {
        int s0 = g_csr[idx + 0], s1 = g_csr[idx + 1];
        int s2 = g_csr[idx + 2], s3 = g_csr[idx + 3];
        unsigned u0 = *(const unsigned*)(hh + (size_t)s0 * 40 + lane * 2);
        unsigned u1 = *(const unsigned*)(hh + (size_t)s1 * 40 + lane * 2);
        unsigned u2 = *(const unsigned*)(hh + (size_t)s2 * 40 + lane * 2);
        unsigned u3 = *(const unsigned*)(hh + (size_t)s3 * 40 + lane * 2);
        float2 f0 = __half22float2(*(const __half2*)&u0);
        float2 f1 = __half22float2(*(const __half2*)&u1);
        float2 f2 = __half22float2(*(const __half2*)&u2);
        float2 f3 = __half22float2(*(const __half2*)&u3);
        acc.x += f0.x + f1.x + f2.x + f3.x;
        acc.y += f0.y + f1.y + f2.y + f3.y;
    }
    for (; idx < end; ++idx) {
        int s = g_csr[idx];
        unsigned u = *(const unsigned*)(hh + (size_t)s * 40 + lane * 2);
        float2 f = __half22float2(*(const __half2*)&u);
        acc.x += f.x; acc.y += f.y;
    }
    float* o = out + (size_t)w * 40 + lane * 2;
    float2 cur = *(const float2*)o;
    cur.x += dd * acc.x; cur.y += dd * acc.y;
    *(float2*)o = cur;
}

// ------------------------------------------------------------------
extern "C" void kernel_launch(void* const* d_in, const int* in_sizes, int n_in,
                              void* d_out, int out_size) {
    const float* x  = (const float*)d_in[0];
    const float* W0 = (const float*)d_in[1];
    const float* b0 = (const float*)d_in[2];
    const float* W1 = (const float*)d_in[3];
    const float* b1 = (const float*)d_in[4];
    const float* W2 = (const float*)d_in[5];
    const float* b2 = (const float*)d_in[6];
    const void*  ei = d_in[7];
    int n = in_sizes[0] / FEAT;
    int E = in_sizes[7] / 2;
    if (E > EMAX) E = EMAX;
    float* out = (float*)d_out;

    __half *pHh, *pH2h, *pAGG;
    cudaGetSymbolAddress((void**)&pHh,  g_Hh);
    cudaGetSymbolAddress((void**)&pH2h, g_H2h);
    cudaGetSymbolAddress((void**)&pAGG, g_AGG);

    const int tb = 256;
    int eblk = (E + tb - 1) / tb;
    int oblk = (n + 255) / 256;
    int gblk = (n + 127) / 128;
    int wblk = (int)(((long long)n * 32 + tb - 1) / tb);

    // CSR build (unordered segments)
    k_count<<<eblk, tb>>>(ei, n, E);
    k_offset<<<oblk, 256>>>(n);
    k_fill<<<eblk, tb>>>(ei, n, E);

    // layer 0 (A = x, fp32)
    k_gemm128h<false, false><<<gblk, 256>>>(x, W0, b0, pHh, pAGG, n);
    k_spmm128<<<wblk, tb>>>(pHh, pAGG, n);
    // layer 1 (A = AGG fp16, ReLU fused)
    k_gemm128h<true, true><<<gblk, 256>>>(pAGG, W1, b1, pHh, pAGG, n);
    k_spmm128<<<wblk, tb>>>(pHh, pAGG, n);
    // layer 2 (A = AGG fp16, relu fused)
    k_gemm40h<<<gblk, 256>>>(pAGG, W2, b2, pH2h, out, n);
    k_spmm40h<<<wblk, tb>>>(pH2h, out, n);
}

// round 8
// speedup vs baseline: 1.2919x; 1.2919x over previous
#include <cuda_runtime.h>
#include <cuda_fp16.h>

#define NN    100000
#define FEAT  128
#define CLS   40
#define EMAX  1600000

// ---- scratch (static device globals; no allocation allowed) ----
__device__ int    g_degi[NN];
__device__ float  g_dinv[NN];
__device__ __half g_Hh[(size_t)NN * FEAT];   // pre-scaled fp16 messages h*dinv
__device__ float  g_AGG[(size_t)NN * FEAT];  // fp32 aggregation buffer
__device__ __half g_H2h[(size_t)NN * CLS];   // layer-2 pre-scaled fp16 messages
__device__ int    g_is64;                    // edge_index dtype flag
__device__ int    g_rowptr[NN + 1];
__device__ int    g_cursor[NN];
__device__ int    g_csr[EMAX];               // src ids grouped by dst
__device__ int    g_bsum[128];
__device__ int    g_boff[128];

// ---- mma helpers ----
__device__ __forceinline__ unsigned sm_u32(const void* p) {
    return (unsigned)__cvta_generic_to_shared(p);
}
__device__ __forceinline__ void ldm_x4(unsigned* r, unsigned a) {
    asm volatile("ldmatrix.sync.aligned.m8n8.x4.shared.b16 {%0,%1,%2,%3}, [%4];"
                 : "=r"(r[0]), "=r"(r[1]), "=r"(r[2]), "=r"(r[3]) : "r"(a));
}
__device__ __forceinline__ void ldm_x4t(unsigned* r, unsigned a) {
    asm volatile("ldmatrix.sync.aligned.m8n8.x4.trans.shared.b16 {%0,%1,%2,%3}, [%4];"
                 : "=r"(r[0]), "=r"(r[1]), "=r"(r[2]), "=r"(r[3]) : "r"(a));
}
__device__ __forceinline__ void mma16816(float* d, const unsigned* a,
                                         const unsigned* b) {
    asm volatile(
        "mma.sync.aligned.m16n8k16.row.col.f32.f16.f16.f32 "
        "{%0,%1,%2,%3},{%4,%5,%6,%7},{%8,%9},{%0,%1,%2,%3};"
        : "+f"(d[0]), "+f"(d[1]), "+f"(d[2]), "+f"(d[3])
        : "r"(a[0]), "r"(a[1]), "r"(a[2]), "r"(a[3]), "r"(b[0]), "r"(b[1]));
}

// ------------------------------------------------------------------
// degree / dinv / CSR build (round-6 proven pipeline)
// ------------------------------------------------------------------
__global__ void k_zero_deg(const void* ei, int n) {
    int i = blockIdx.x * blockDim.x + threadIdx.x;
    if (i < n) g_degi[i] = 0;
    if (i == 0) {
        const unsigned long long* p = (const unsigned long long*)ei;
        g_is64 = (p[0] < (unsigned long long)n && p[1] < (unsigned long long)n) ? 1 : 0;
    }
}

__global__ void k_count(const void* ei, int E) {
    int e = blockIdx.x * blockDim.x + threadIdx.x;
    if (e >= E) return;
    int dst;
    if (g_is64) dst = (int)((const long long*)ei)[E + e];
    else        dst = ((const int*)ei)[E + e];
    atomicAdd(&g_degi[dst], 1);
}

// scanA also produces dinv (fused)
__global__ void k_scanA(int n) {
    __shared__ int s[1024];
    int i = blockIdx.x * 1024 + threadIdx.x;
    int v = (i < n) ? g_degi[i] : 0;
    if (i < n) g_dinv[i] = rsqrtf((float)v + 1.f);
    s[threadIdx.x] = v;
    __syncthreads();
#pragma unroll
    for (int off = 1; off < 1024; off <<= 1) {
        int x = (threadIdx.x >= off) ? s[threadIdx.x - off] : 0;
        __syncthreads();
        s[threadIdx.x] += x;
        __syncthreads();
    }
    if (i < n) g_rowptr[i] = s[threadIdx.x] - v;
    if (threadIdx.x == 1023) g_bsum[blockIdx.x] = s[1023];
}

__global__ void k_scanB(int nb) {
    __shared__ int s[128];
    int t = threadIdx.x;
    int v = (t < nb) ? g_bsum[t] : 0;
    s[t] = v;
    __syncthreads();
#pragma unroll
    for (int off = 1; off < 128; off <<= 1) {
        int x = (t >= off) ? s[t - off] : 0;
        __syncthreads();
        s[t] += x;
        __syncthreads();
    }
    g_boff[t] = s[t] - v;
}

__global__ void k_scanC(int n, int E) {
    int i = blockIdx.x * 1024 + threadIdx.x;
    if (i < n) {
        int r = g_rowptr[i] + g_boff[blockIdx.x];
        g_rowptr[i] = r;
        g_cursor[i] = r;
    }
    if (i == 0) g_rowptr[n] = E;
}

__global__ void k_fill(const void* ei, int E) {
    int e = blockIdx.x * blockDim.x + threadIdx.x;
    if (e >= E) return;
    int s, d;
    if (g_is64) {
        const long long* p = (const long long*)ei;
        s = (int)p[e]; d = (int)p[E + e];
    } else {
        const int* p = (const int*)ei;
        s = p[e]; d = p[E + e];
    }
    int pos = atomicAdd(&g_cursor[d], 1);
    g_csr[pos] = s;
}

// ------------------------------------------------------------------
// Tensor-core GEMM (K=128, Nout=128): h = act(A) @ W  (fp16 in, fp32 acc)
//   Hh  = half(h * dinv)    (pre-scaled message)
//   AGG = h * dinv^2 + b    (self-loop + bias, fp32)
// BM=128, BN=128, BK=64, 8 warps (4x2), warp tile 32x64, mma 16x8x16
// Epilogue staged through smem for fully coalesced global stores.
// ------------------------------------------------------------------
#define AS(r, c) sbuf[(r) * 72 + (c)]
#define WS(r, c) sbuf[9216 + (r) * 136 + (c)]
#define HS(r, c) sbuf[(r) * 136 + (c)]

template <bool RELU>
__global__ __launch_bounds__(256, 2)
void k_gemm128h(const float* __restrict__ A, const float* __restrict__ W,
                const float* __restrict__ b, __half* __restrict__ Hh,
                float* __restrict__ AGG, int n) {
    // As: 128x72 halves (9216) | Ws: 64x136 halves (8704)  => 17920 halves
    // Hs (epilogue overlay): 128x136 halves (17408) fits in the same buffer
    __shared__ __half sbuf[17920];
    const int tid  = threadIdx.x;
    const int lane = tid & 31;
    const int warp = tid >> 5;
    const int wm   = warp & 3;
    const int wn   = warp >> 2;
    const int row0 = blockIdx.x * 128;

    float acc[2][8][4];
#pragma unroll
    for (int mi = 0; mi < 2; mi++)
#pragma unroll
        for (int ni = 0; ni < 8; ni++)
#pragma unroll
            for (int q = 0; q < 4; q++) acc[mi][ni][q] = 0.f;

    const int ar = tid >> 1, ac = (tid & 1) * 32;
    const int wr = tid >> 2, wc = (tid & 3) * 32;

#pragma unroll
    for (int kb = 0; kb < 2; kb++) {
        if (kb) __syncthreads();
        // A tile -> fp16 smem (relu fused)
        {
            int gr = row0 + ar;
            const float* Arow = A + (size_t)gr * 128 + kb * 64 + ac;
#pragma unroll
            for (int u = 0; u < 4; u++) {
                float4 f0 = make_float4(0.f, 0.f, 0.f, 0.f), f1 = f0;
                if (gr < n) {
                    f0 = *(const float4*)(Arow + u * 8);
                    f1 = *(const float4*)(Arow + u * 8 + 4);
                }
                if (RELU) {
                    f0.x = fmaxf(f0.x, 0.f); f0.y = fmaxf(f0.y, 0.f);
                    f0.z = fmaxf(f0.z, 0.f); f0.w = fmaxf(f0.w, 0.f);
                    f1.x = fmaxf(f1.x, 0.f); f1.y = fmaxf(f1.y, 0.f);
                    f1.z = fmaxf(f1.z, 0.f); f1.w = fmaxf(f1.w, 0.f);
                }
                __half2 hh[4];
                hh[0] = __floats2half2_rn(f0.x, f0.y);
                hh[1] = __floats2half2_rn(f0.z, f0.w);
                hh[2] = __floats2half2_rn(f1.x, f1.y);
                hh[3] = __floats2half2_rn(f1.z, f1.w);
                *(uint4*)&AS(ar, ac + u * 8) = *(uint4*)hh;
            }
        }
        // W tile -> fp16 smem
        {
            const float* Wrow = W + (size_t)(kb * 64 + wr) * 128 + wc;
#pragma unroll
            for (int u = 0; u < 4; u++) {
                float4 f0 = *(const float4*)(Wrow + u * 8);
                float4 f1 = *(const float4*)(Wrow + u * 8 + 4);
                __half2 hh[4];
                hh[0] = __floats2half2_rn(f0.x, f0.y);
                hh[1] = __floats2half2_rn(f0.z, f0.w);
                hh[2] = __floats2half2_rn(f1.x, f1.y);
                hh[3] = __floats2half2_rn(f1.z, f1.w);
                *(uint4*)&WS(wr, wc + u * 8) = *(uint4*)hh;
            }
        }
        __syncthreads();

#pragma unroll
        for (int kk = 0; kk < 4; kk++) {
            unsigned af[2][4];
#pragma unroll
            for (int mi = 0; mi < 2; mi++) {
                int r = wm * 32 + mi * 16 + (lane & 15);
                int kh = kk * 16 + (lane >> 4) * 8;
                ldm_x4(af[mi], sm_u32(&AS(r, kh)));
            }
            unsigned bf[8][2];
#pragma unroll
            for (int nt = 0; nt < 4; nt++) {
                int g = lane >> 3, r = lane & 7;
                int krow = kk * 16 + (g & 1) * 8 + r;
                int ncol = wn * 64 + nt * 16 + (g >> 1) * 8;
                unsigned t[4];
                ldm_x4t(t, sm_u32(&WS(krow, ncol)));
                bf[nt * 2 + 0][0] = t[0]; bf[nt * 2 + 0][1] = t[1];
                bf[nt * 2 + 1][0] = t[2]; bf[nt * 2 + 1][1] = t[3];
            }
#pragma unroll
            for (int mi = 0; mi < 2; mi++)
#pragma unroll
                for (int ni = 0; ni < 8; ni++)
                    mma16816(acc[mi][ni], af[mi], bf[ni]);
        }
    }

    // ---- epilogue: stage h (fp16) into smem, then coalesced stores ----
    __syncthreads();   // done reading As/Ws
    {
        const int r1 = lane >> 2;
        const int c2 = (lane & 3) * 2;
#pragma unroll
        for (int mi = 0; mi < 2; mi++) {
            int r = wm * 32 + mi * 16 + r1;
#pragma unroll
            for (int ni = 0; ni < 8; ni++) {
                int col = wn * 64 + ni * 8 + c2;
                __half2 h01 = __floats2half2_rn(acc[mi][ni][0], acc[mi][ni][1]);
                __half2 h23 = __floats2half2_rn(acc[mi][ni][2], acc[mi][ni][3]);
                *(__half2*)&HS(r, col)     = h01;
                *(__half2*)&HS(r + 8, col) = h23;
            }
        }
    }
    __syncthreads();

    // pass 1: Hh = h * dinv  (fp16, 512B coalesced per warp)
    {
        int rrow  = tid >> 4;    // 0..15
        int chunk = tid & 15;    // 16 x uint4 chunks per 128-col row
#pragma unroll
        for (int p = 0; p < 8; p++) {
            int r = p * 16 + rrow;
            int gr = row0 + r;
            if (gr < n) {
                __half2 d2 = __float2half2_rn(g_dinv[gr]);
                uint4 u = *(uint4*)&HS(r, chunk * 8);
                __half2* hp = (__half2*)&u;
                hp[0] = __hmul2(hp[0], d2); hp[1] = __hmul2(hp[1], d2);
                hp[2] = __hmul2(hp[2], d2); hp[3] = __hmul2(hp[3], d2);
                *(uint4*)(Hh + (size_t)gr * 128 + chunk * 8) = u;
            }
        }
    }
    // pass 2: AGG = h * dinv^2 + b  (fp32, 512B coalesced per warp)
    {
        int rrow  = tid >> 5;    // 0..7
        int chunk = tid & 31;    // 32 x float4 chunks per row
        float4 bv = *(const float4*)(b + chunk * 4);
#pragma unroll
        for (int p = 0; p < 16; p++) {
            int r = p * 8 + rrow;
            int gr = row0 + r;
            if (gr < n) {
                float di = g_dinv[gr];
                float dd = di * di;
                uint2 u = *(uint2*)&HS(r, chunk * 4);
                float2 f0 = __half22float2(*(__half2*)&u.x);
                float2 f1 = __half22float2(*(__half2*)&u.y);
                float4 g = make_float4(f0.x * dd + bv.x, f0.y * dd + bv.y,
                                       f1.x * dd + bv.z, f1.y * dd + bv.w);
                *(float4*)(AGG + (size_t)gr * 128 + chunk * 4) = g;
            }
        }
    }
}

// ------------------------------------------------------------------
// Tensor-core GEMM (K=128, Nout=40 padded to 64), fp32 A:
//   h2  = relu(A) @ W2
//   H2h = half(h2 * dinv) ; OUT = h2 * dinv^2 + b2 (fp32)
// ------------------------------------------------------------------
__global__ __launch_bounds__(256, 2)
void k_gemm40h(const float* __restrict__ A, const float* __restrict__ W,
               const float* __restrict__ b, __half* __restrict__ H2h,
               float* __restrict__ OUT, int n) {
    __shared__ __half As[128][72];
    __shared__ __half Ws[64][72];    // [k][n] 64 cols (40 real, rest 0)
    const int tid  = threadIdx.x;
    const int lane = tid & 31;
    const int warp = tid >> 5;
    const int wm   = warp & 3;
    const int wn   = warp >> 2;
    const int row0 = blockIdx.x * 128;

    float acc[2][4][4];
#pragma unroll
    for (int mi = 0; mi < 2; mi++)
#pragma unroll
        for (int ni = 0; ni < 4; ni++)
#pragma unroll
            for (int q = 0; q < 4; q++) acc[mi][ni][q] = 0.f;

    const int ar = tid >> 1, ac = (tid & 1) * 32;

#pragma unroll
    for (int kb = 0; kb < 2; kb++) {
        if (kb) __syncthreads();
        {
            int gr = row0 + ar;
            const float* Arow = A + (size_t)gr * 128 + kb * 64 + ac;
#pragma unroll
            for (int u = 0; u < 4; u++) {
                float4 f0 = make_float4(0.f, 0.f, 0.f, 0.f), f1 = f0;
                if (gr < n) {
                    f0 = *(const float4*)(Arow + u * 8);
                    f1 = *(const float4*)(Arow + u * 8 + 4);
                }
                f0.x = fmaxf(f0.x, 0.f); f0.y = fmaxf(f0.y, 0.f);
                f0.z = fmaxf(f0.z, 0.f); f0.w = fmaxf(f0.w, 0.f);
                f1.x = fmaxf(f1.x, 0.f); f1.y = fmaxf(f1.y, 0.f);
                f1.z = fmaxf(f1.z, 0.f); f1.w = fmaxf(f1.w, 0.f);
                __half2 hh[4];
                hh[0] = __floats2half2_rn(f0.x, f0.y);
                hh[1] = __floats2half2_rn(f0.z, f0.w);
                hh[2] = __floats2half2_rn(f1.x, f1.y);
                hh[3] = __floats2half2_rn(f1.z, f1.w);
                *(uint4*)&As[ar][ac + u * 8] = *(uint4*)hh;
            }
        }
        for (int idx = tid; idx < 64 * 64; idx += 256) {
            int k = idx >> 6, c = idx & 63;
            float v = (c < 40) ? W[(size_t)(kb * 64 + k) * 40 + c] : 0.f;
            Ws[k][c] = __float2half_rn(v);
        }
        __syncthreads();

#pragma unroll
        for (int kk = 0; kk < 4; kk++) {
            unsigned af[2][4];
#pragma unroll
            for (int mi = 0; mi < 2; mi++) {
                int r = wm * 32 + mi * 16 + (lane & 15);
                int kh = kk * 16 + (lane >> 4) * 8;
                ldm_x4(af[mi], sm_u32(&As[r][kh]));
            }
            unsigned bf[4][2];
#pragma unroll
            for (int nt = 0; nt < 2; nt++) {
                int g = lane >> 3, r = lane & 7;
                int krow = kk * 16 + (g & 1) * 8 + r;
                int ncol = wn * 32 + nt * 16 + (g >> 1) * 8;
                unsigned t[4];
                ldm_x4t(t, sm_u32(&Ws[krow][ncol]));
                bf[nt * 2 + 0][0] = t[0]; bf[nt * 2 + 0][1] = t[1];
                bf[nt * 2 + 1][0] = t[2]; bf[nt * 2 + 1][1] = t[3];
            }
#pragma unroll
            for (int mi = 0; mi < 2; mi++)
#pragma unroll
                for (int ni = 0; ni < 4; ni++)
                    mma16816(acc[mi][ni], af[mi], bf[ni]);
        }
    }

    const int r1 = lane >> 2;
    const int c2 = (lane & 3) * 2;
#pragma unroll
    for (int mi = 0; mi < 2; mi++) {
        int gr0 = row0 + wm * 32 + mi * 16 + r1;
        int gr1 = gr0 + 8;
        float d0 = (gr0 < n) ? g_dinv[gr0] : 0.f;
        float d1 = (gr1 < n) ? g_dinv[gr1] : 0.f;
        float dd0 = d0 * d0, dd1 = d1 * d1;
#pragma unroll
        for (int ni = 0; ni < 4; ni++) {
            int col = wn * 32 + ni * 8 + c2;
            if (col >= 40) continue;
            float bx = b[col], by = b[col + 1];
            float c0 = acc[mi][ni][0], c1 = acc[mi][ni][1];
            float c3 = acc[mi][ni][2], c4 = acc[mi][ni][3];
            if (gr0 < n) {
                __half2 h = __floats2half2_rn(c0 * d0, c1 * d0);
                *(unsigned*)(H2h + (size_t)gr0 * 40 + col) = *(unsigned*)&h;
                *(float2*)(OUT + (size_t)gr0 * 40 + col) =
                    make_float2(c0 * dd0 + bx, c1 * dd0 + by);
            }
            if (gr1 < n) {
                __half2 h = __floats2half2_rn(c3 * d1, c4 * d1);
                *(unsigned*)(H2h + (size_t)gr1 * 40 + col) = *(unsigned*)&h;
                *(float2*)(OUT + (size_t)gr1 * 40 + col) =
                    make_float2(c3 * dd1 + bx, c4 * dd1 + by);
            }
        }
    }
}

// ------------------------------------------------------------------
// SpMM aggregation (fp16 pre-scaled messages, fp32 AGG):
//   AGG[d] += dinv[d] * sum_{s in row d} Hh[s]
// ------------------------------------------------------------------
__global__ __launch_bounds__(256)
void k_spmm128(const __half* __restrict__ hh, float* __restrict__ agg, int n) {
    int w = (blockIdx.x * blockDim.x + threadIdx.x) >> 5;
    if (w >= n) return;
    int lane = threadIdx.x & 31;
    int beg = g_rowptr[w];
    int end = g_rowptr[w + 1];
    float dd = g_dinv[w];
    float4 acc = make_float4(0.f, 0.f, 0.f, 0.f);

    int idx = beg;
    for (; idx + 4 <= end; idx += 4) {
        int s0 = g_csr[idx + 0], s1 = g_csr[idx + 1];
        int s2 = g_csr[idx + 2], s3 = g_csr[idx + 3];
        uint2 u0 = *(const uint2*)(hh + (size_t)s0 * 128 + lane * 4);
        uint2 u1 = *(const uint2*)(hh + (size_t)s1 * 128 + lane * 4);
        uint2 u2 = *(const uint2*)(hh + (size_t)s2 * 128 + lane * 4);
        uint2 u3 = *(const uint2*)(hh + (size_t)s3 * 128 + lane * 4);
#pragma unroll
        for (int q = 0; q < 4; q++) {
            uint2 u = (q == 0) ? u0 : (q == 1) ? u1 : (q == 2) ? u2 : u3;
            float2 f0 = __half22float2(*(const __half2*)&u.x);
            float2 f1 = __half22float2(*(const __half2*)&u.y);
            acc.x += f0.x; acc.y += f0.y; acc.z += f1.x; acc.w += f1.y;
        }
    }
    for (; idx < end; ++idx) {
        int s = g_csr[idx];
        uint2 u = *(const uint2*)(hh + (size_t)s * 128 + lane * 4);
        float2 f0 = __half22float2(*(const __half2*)&u.x);
        float2 f1 = __half22float2(*(const __half2*)&u.y);
        acc.x += f0.x; acc.y += f0.y; acc.z += f1.x; acc.w += f1.y;
    }
    float* o = agg + (size_t)w * 128 + lane * 4;
    float4 cur = *(const float4*)o;
    cur.x += dd * acc.x; cur.y += dd * acc.y;
    cur.z += dd * acc.z; cur.w += dd * acc.w;
    *(float4*)o = cur;
}

// layer-2 spmm on fp16 pre-scaled messages (20 lanes x 2 cols), fp32 out
__global__ __launch_bounds__(256)
void k_spmm40h(const __half* __restrict__ hh, float* __restrict__ out, int n) {
    int w = (blockIdx.x * blockDim.x + threadIdx.x) >> 5;
    if (w >= n) return;
    int lane = threadIdx.x & 31;
    if (lane >= 20) return;
    int beg = g_rowptr[w];
    int end = g_rowptr[w + 1];
    float dd = g_dinv[w];
    float2 acc = make_float2(0.f, 0.f);

    int idx = beg;
    for (; idx + 4 <= end; idx += 4) {
        int s0 = g_csr[idx + 0], s1 = g_csr[idx + 1];
        int s2 = g_csr[idx + 2], s3 = g_csr[idx + 3];
        unsigned u0 = *(const unsigned*)(hh + (size_t)s0 * 40 + lane * 2);
        unsigned u1 = *(const unsigned*)(hh + (size_t)s1 * 40 + lane * 2);
        unsigned u2 = *(const unsigned*)(hh + (size_t)s2 * 40 + lane * 2);
        unsigned u3 = *(const unsigned*)(hh + (size_t)s3 * 40 + lane * 2);
        float2 f0 = __half22float2(*(const __half2*)&u0);
        float2 f1 = __half22float2(*(const __half2*)&u1);
        float2 f2 = __half22float2(*(const __half2*)&u2);
        float2 f3 = __half22float2(*(const __half2*)&u3);
        acc.x += f0.x + f1.x + f2.x + f3.x;
        acc.y += f0.y + f1.y + f2.y + f3.y;
    }
    for (; idx < end; ++idx) {
        int s = g_csr[idx];
        unsigned u = *(const unsigned*)(hh + (size_t)s * 40 + lane * 2);
        float2 f = __half22float2(*(const __half2*)&u);
        acc.x += f.x; acc.y += f.y;
    }
    float* o = out + (size_t)w * 40 + lane * 2;
    float2 cur = *(const float2*)o;
    cur.x += dd * acc.x; cur.y += dd * acc.y;
    *(float2*)o = cur;
}

// ------------------------------------------------------------------
extern "C" void kernel_launch(void* const* d_in, const int* in_sizes, int n_in,
                              void* d_out, int out_size) {
    const float* x  = (const float*)d_in[0];
    const float* W0 = (const float*)d_in[1];
    const float* b0 = (const float*)d_in[2];
    const float* W1 = (const float*)d_in[3];
    const float* b1 = (const float*)d_in[4];
    const float* W2 = (const float*)d_in[5];
    const float* b2 = (const float*)d_in[6];
    const void*  ei = d_in[7];
    int n = in_sizes[0] / FEAT;
    int E = in_sizes[7] / 2;
    if (E > EMAX) E = EMAX;
    float* out = (float*)d_out;

    __half *pHh, *pH2h; float* pAGG;
    cudaGetSymbolAddress((void**)&pHh,  g_Hh);
    cudaGetSymbolAddress((void**)&pH2h, g_H2h);
    cudaGetSymbolAddress((void**)&pAGG, g_AGG);

    const int tb = 256;
    int nblk  = (n + tb - 1) / tb;
    int eblk  = (E + tb - 1) / tb;
    int gblk  = (n + 127) / 128;
    int scblk = (n + 1023) / 1024;
    int wblk  = (int)(((long long)n * 32 + tb - 1) / tb);

    // degree + CSR build
    k_zero_deg<<<nblk, tb>>>(ei, n);
    k_count<<<eblk, tb>>>(ei, E);
    k_scanA<<<scblk, 1024>>>(n);
    k_scanB<<<1, 128>>>(scblk);
    k_scanC<<<scblk, 1024>>>(n, E);
    k_fill<<<eblk, tb>>>(ei, E);

    // layer 0
    k_gemm128h<false><<<gblk, 256>>>(x, W0, b0, pHh, pAGG, n);
    k_spmm128<<<wblk, tb>>>(pHh, pAGG, n);
    // layer 1 (ReLU fused into next GEMM's A-load)
    k_gemm128h<true><<<gblk, 256>>>(pAGG, W1, b1, pHh, pAGG, n);
    k_spmm128<<<wblk, tb>>>(pHh, pAGG, n);
    // layer 2 (tensor-core, relu fused; fp16 pre-scaled messages)
    k_gemm40h<<<gblk, 256>>>(pAGG, W2, b2, pH2h, out, n);
    k_spmm40h<<<wblk, tb>>>(pH2h, out, n);
}

// round 9
// speedup vs baseline: 1.3468x; 1.0425x over previous
#include <cuda_runtime.h>
#include <cuda_fp16.h>

#define NN    100000
#define FEAT  128
#define CLS   40
#define EMAX  1600000

// ---- scratch (static device globals; no allocation allowed) ----
__device__ int    g_degi[NN];
__device__ float  g_dinv[NN];
__device__ __half g_Hh[(size_t)NN * FEAT];   // pre-scaled fp16 messages h*dinv
__device__ float  g_AGG[(size_t)NN * FEAT];  // fp32 aggregation buffer
__device__ __half g_H2h[(size_t)NN * CLS];   // layer-2 pre-scaled fp16 messages
__device__ int    g_is64;                    // edge_index dtype flag
__device__ int    g_rowptr[NN + 1];
__device__ int    g_cursor[NN];
__device__ int    g_csr[EMAX];               // src ids grouped by dst
__device__ int    g_bsum[128];
__device__ int    g_boff[128];

// ---- mma helpers ----
__device__ __forceinline__ unsigned sm_u32(const void* p) {
    return (unsigned)__cvta_generic_to_shared(p);
}
__device__ __forceinline__ void ldm_x4(unsigned* r, unsigned a) {
    asm volatile("ldmatrix.sync.aligned.m8n8.x4.shared.b16 {%0,%1,%2,%3}, [%4];"
                 : "=r"(r[0]), "=r"(r[1]), "=r"(r[2]), "=r"(r[3]) : "r"(a));
}
__device__ __forceinline__ void ldm_x4t(unsigned* r, unsigned a) {
    asm volatile("ldmatrix.sync.aligned.m8n8.x4.trans.shared.b16 {%0,%1,%2,%3}, [%4];"
                 : "=r"(r[0]), "=r"(r[1]), "=r"(r[2]), "=r"(r[3]) : "r"(a));
}
__device__ __forceinline__ void mma16816(float* d, const unsigned* a,
                                         const unsigned* b) {
    asm volatile(
        "mma.sync.aligned.m16n8k16.row.col.f32.f16.f16.f32 "
        "{%0,%1,%2,%3},{%4,%5,%6,%7},{%8,%9},{%0,%1,%2,%3};"
        : "+f"(d[0]), "+f"(d[1]), "+f"(d[2]), "+f"(d[3])
        : "r"(a[0]), "r"(a[1]), "r"(a[2]), "r"(a[3]), "r"(b[0]), "r"(b[1]));
}

// ------------------------------------------------------------------
// degree / dinv / CSR build
// ------------------------------------------------------------------
__global__ void k_zero_deg(const void* ei, int n) {
    int i = blockIdx.x * blockDim.x + threadIdx.x;
    if (i < n) g_degi[i] = 0;
    if (i == 0) {
        const unsigned long long* p = (const unsigned long long*)ei;
        g_is64 = (p[0] < (unsigned long long)n && p[1] < (unsigned long long)n) ? 1 : 0;
    }
}

__global__ void k_count(const void* ei, int E) {
    int e = blockIdx.x * blockDim.x + threadIdx.x;
    if (e >= E) return;
    int dst;
    if (g_is64) dst = (int)((const long long*)ei)[E + e];
    else        dst = ((const int*)ei)[E + e];
    atomicAdd(&g_degi[dst], 1);
}

// scanA also produces dinv (fused)
__global__ void k_scanA(int n) {
    __shared__ int s[1024];
    int i = blockIdx.x * 1024 + threadIdx.x;
    int v = (i < n) ? g_degi[i] : 0;
    if (i < n) g_dinv[i] = rsqrtf((float)v + 1.f);
    s[threadIdx.x] = v;
    __syncthreads();
#pragma unroll
    for (int off = 1; off < 1024; off <<= 1) {
        int x = (threadIdx.x >= off) ? s[threadIdx.x - off] : 0;
        __syncthreads();
        s[threadIdx.x] += x;
        __syncthreads();
    }
    if (i < n) g_rowptr[i] = s[threadIdx.x] - v;
    if (threadIdx.x == 1023) g_bsum[blockIdx.x] = s[1023];
}

__global__ void k_scanB(int nb) {
    __shared__ int s[128];
    int t = threadIdx.x;
    int v = (t < nb) ? g_bsum[t] : 0;
    s[t] = v;
    __syncthreads();
#pragma unroll
    for (int off = 1; off < 128; off <<= 1) {
        int x = (t >= off) ? s[t - off] : 0;
        __syncthreads();
        s[t] += x;
        __syncthreads();
    }
    g_boff[t] = s[t] - v;
}

__global__ void k_scanC(int n, int E) {
    int i = blockIdx.x * 1024 + threadIdx.x;
    if (i < n) {
        int r = g_rowptr[i] + g_boff[blockIdx.x];
        g_rowptr[i] = r;
        g_cursor[i] = r;
    }
    if (i == 0) g_rowptr[n] = E;
}

__global__ void k_fill(const void* ei, int E) {
    int e = blockIdx.x * blockDim.x + threadIdx.x;
    if (e >= E) return;
    int s, d;
    if (g_is64) {
        const long long* p = (const long long*)ei;
        s = (int)p[e]; d = (int)p[E + e];
    } else {
        const int* p = (const int*)ei;
        s = p[e]; d = p[E + e];
    }
    int pos = atomicAdd(&g_cursor[d], 1);
    g_csr[pos] = s;
}

// ------------------------------------------------------------------
// Tensor-core GEMM (K=128, Nout=128), SINGLE-SHOT smem (no k-loop):
//   h   = act(A) @ W   (fp16 in, fp32 acc)
//   Hh  = half(h * dinv) ; AGG = h * dinv^2 + b (fp32)
// BM=128, BN=128, 8 warps (4x2), warp tile 32x64, mma 16x8x16
// Dynamic smem: As 128x136 + Ws 128x136 halves = 69632 B.
// ------------------------------------------------------------------
#define SPITCH 136
#define AS(r, c) dsm[(r) * SPITCH + (c)]
#define WS(r, c) dsm[17408 + (r) * SPITCH + (c)]
#define HS(r, c) dsm[(r) * SPITCH + (c)]

template <bool RELU>
__global__ __launch_bounds__(256)
void k_gemm128h(const float* __restrict__ A, const float* __restrict__ W,
                const float* __restrict__ b, __half* __restrict__ Hh,
                float* __restrict__ AGG, int n) {
    extern __shared__ __half dsm[];
    const int tid  = threadIdx.x;
    const int lane = tid & 31;
    const int warp = tid >> 5;
    const int wm   = warp & 3;
    const int wn   = warp >> 2;
    const int row0 = blockIdx.x * 128;

    float acc[2][8][4];
#pragma unroll
    for (int mi = 0; mi < 2; mi++)
#pragma unroll
        for (int ni = 0; ni < 8; ni++)
#pragma unroll
            for (int q = 0; q < 4; q++) acc[mi][ni][q] = 0.f;

    // full-tile loads: each thread handles 64 floats of one row
    const int ar = tid >> 1, ac = (tid & 1) * 64;
    {
        int gr = row0 + ar;
        const float* Arow = A + (size_t)gr * 128 + ac;
#pragma unroll
        for (int u = 0; u < 8; u++) {
            float4 f0 = make_float4(0.f, 0.f, 0.f, 0.f), f1 = f0;
            if (gr < n) {
                f0 = *(const float4*)(Arow + u * 8);
                f1 = *(const float4*)(Arow + u * 8 + 4);
            }
            if (RELU) {
                f0.x = fmaxf(f0.x, 0.f); f0.y = fmaxf(f0.y, 0.f);
                f0.z = fmaxf(f0.z, 0.f); f0.w = fmaxf(f0.w, 0.f);
                f1.x = fmaxf(f1.x, 0.f); f1.y = fmaxf(f1.y, 0.f);
                f1.z = fmaxf(f1.z, 0.f); f1.w = fmaxf(f1.w, 0.f);
            }
            __half2 hh[4];
            hh[0] = __floats2half2_rn(f0.x, f0.y);
            hh[1] = __floats2half2_rn(f0.z, f0.w);
            hh[2] = __floats2half2_rn(f1.x, f1.y);
            hh[3] = __floats2half2_rn(f1.z, f1.w);
            *(uint4*)&AS(ar, ac + u * 8) = *(uint4*)hh;
        }
    }
    {
        const float* Wrow = W + (size_t)ar * 128 + ac;
#pragma unroll
        for (int u = 0; u < 8; u++) {
            float4 f0 = *(const float4*)(Wrow + u * 8);
            float4 f1 = *(const float4*)(Wrow + u * 8 + 4);
            __half2 hh[4];
            hh[0] = __floats2half2_rn(f0.x, f0.y);
            hh[1] = __floats2half2_rn(f0.z, f0.w);
            hh[2] = __floats2half2_rn(f1.x, f1.y);
            hh[3] = __floats2half2_rn(f1.z, f1.w);
            *(uint4*)&WS(ar, ac + u * 8) = *(uint4*)hh;
        }
    }
    __syncthreads();

#pragma unroll
    for (int kk = 0; kk < 8; kk++) {
        unsigned af[2][4];
#pragma unroll
        for (int mi = 0; mi < 2; mi++) {
            int r = wm * 32 + mi * 16 + (lane & 15);
            int kh = kk * 16 + (lane >> 4) * 8;
            ldm_x4(af[mi], sm_u32(&AS(r, kh)));
        }
        unsigned bf[8][2];
#pragma unroll
        for (int nt = 0; nt < 4; nt++) {
            int g = lane >> 3, r = lane & 7;
            int krow = kk * 16 + (g & 1) * 8 + r;
            int ncol = wn * 64 + nt * 16 + (g >> 1) * 8;
            unsigned t[4];
            ldm_x4t(t, sm_u32(&WS(krow, ncol)));
            bf[nt * 2 + 0][0] = t[0]; bf[nt * 2 + 0][1] = t[1];
            bf[nt * 2 + 1][0] = t[2]; bf[nt * 2 + 1][1] = t[3];
        }
#pragma unroll
        for (int mi = 0; mi < 2; mi++)
#pragma unroll
            for (int ni = 0; ni < 8; ni++)
                mma16816(acc[mi][ni], af[mi], bf[ni]);
    }

    // ---- epilogue: stage h (fp16) into smem, then coalesced stores ----
    __syncthreads();
    {
        const int r1 = lane >> 2;
        const int c2 = (lane & 3) * 2;
#pragma unroll
        for (int mi = 0; mi < 2; mi++) {
            int r = wm * 32 + mi * 16 + r1;
#pragma unroll
            for (int ni = 0; ni < 8; ni++) {
                int col = wn * 64 + ni * 8 + c2;
                __half2 h01 = __floats2half2_rn(acc[mi][ni][0], acc[mi][ni][1]);
                __half2 h23 = __floats2half2_rn(acc[mi][ni][2], acc[mi][ni][3]);
                *(__half2*)&HS(r, col)     = h01;
                *(__half2*)&HS(r + 8, col) = h23;
            }
        }
    }
    __syncthreads();

    // pass 1: Hh = h * dinv (fp16, coalesced)
    {
        int rrow  = tid >> 4;
        int chunk = tid & 15;
#pragma unroll
        for (int p = 0; p < 8; p++) {
            int r = p * 16 + rrow;
            int gr = row0 + r;
            if (gr < n) {
                __half2 d2 = __float2half2_rn(g_dinv[gr]);
                uint4 u = *(uint4*)&HS(r, chunk * 8);
                __half2* hp = (__half2*)&u;
                hp[0] = __hmul2(hp[0], d2); hp[1] = __hmul2(hp[1], d2);
                hp[2] = __hmul2(hp[2], d2); hp[3] = __hmul2(hp[3], d2);
                *(uint4*)(Hh + (size_t)gr * 128 + chunk * 8) = u;
            }
        }
    }
    // pass 2: AGG = h * dinv^2 + b (fp32, coalesced)
    {
        int rrow  = tid >> 5;
        int chunk = tid & 31;
        float4 bv = *(const float4*)(b + chunk * 4);
#pragma unroll
        for (int p = 0; p < 16; p++) {
            int r = p * 8 + rrow;
            int gr = row0 + r;
            if (gr < n) {
                float di = g_dinv[gr];
                float dd = di * di;
                uint2 u = *(uint2*)&HS(r, chunk * 4);
                float2 f0 = __half22float2(*(__half2*)&u.x);
                float2 f1 = __half22float2(*(__half2*)&u.y);
                float4 g = make_float4(f0.x * dd + bv.x, f0.y * dd + bv.y,
                                       f1.x * dd + bv.z, f1.y * dd + bv.w);
                *(float4*)(AGG + (size_t)gr * 128 + chunk * 4) = g;
            }
        }
    }
}

// ------------------------------------------------------------------
// Tensor-core GEMM (K=128, Nout=40 padded to 64), fp32 A:
//   h2  = relu(A) @ W2 ; H2h = half(h2*dinv) ; OUT = h2*dinv^2 + b2
// ------------------------------------------------------------------
__global__ __launch_bounds__(256, 2)
void k_gemm40h(const float* __restrict__ A, const float* __restrict__ W,
               const float* __restrict__ b, __half* __restrict__ H2h,
               float* __restrict__ OUT, int n) {
    __shared__ __half As[128][72];
    __shared__ __half Ws[64][72];
    const int tid  = threadIdx.x;
    const int lane = tid & 31;
    const int warp = tid >> 5;
    const int wm   = warp & 3;
    const int wn   = warp >> 2;
    const int row0 = blockIdx.x * 128;

    float acc[2][4][4];
#pragma unroll
    for (int mi = 0; mi < 2; mi++)
#pragma unroll
        for (int ni = 0; ni < 4; ni++)
#pragma unroll
            for (int q = 0; q < 4; q++) acc[mi][ni][q] = 0.f;

    const int ar = tid >> 1, ac = (tid & 1) * 32;

#pragma unroll
    for (int kb = 0; kb < 2; kb++) {
        if (kb) __syncthreads();
        {
            int gr = row0 + ar;
            const float* Arow = A + (size_t)gr * 128 + kb * 64 + ac;
#pragma unroll
            for (int u = 0; u < 4; u++) {
                float4 f0 = make_float4(0.f, 0.f, 0.f, 0.f), f1 = f0;
                if (gr < n) {
                    f0 = *(const float4*)(Arow + u * 8);
                    f1 = *(const float4*)(Arow + u * 8 + 4);
                }
                f0.x = fmaxf(f0.x, 0.f); f0.y = fmaxf(f0.y, 0.f);
                f0.z = fmaxf(f0.z, 0.f); f0.w = fmaxf(f0.w, 0.f);
                f1.x = fmaxf(f1.x, 0.f); f1.y = fmaxf(f1.y, 0.f);
                f1.z = fmaxf(f1.z, 0.f); f1.w = fmaxf(f1.w, 0.f);
                __half2 hh[4];
                hh[0] = __floats2half2_rn(f0.x, f0.y);
                hh[1] = __floats2half2_rn(f0.z, f0.w);
                hh[2] = __floats2half2_rn(f1.x, f1.y);
                hh[3] = __floats2half2_rn(f1.z, f1.w);
                *(uint4*)&As[ar][ac + u * 8] = *(uint4*)hh;
            }
        }
        for (int idx = tid; idx < 64 * 64; idx += 256) {
            int k = idx >> 6, c = idx & 63;
            float v = (c < 40) ? W[(size_t)(kb * 64 + k) * 40 + c] : 0.f;
            Ws[k][c] = __float2half_rn(v);
        }
        __syncthreads();

#pragma unroll
        for (int kk = 0; kk < 4; kk++) {
            unsigned af[2][4];
#pragma unroll
            for (int mi = 0; mi < 2; mi++) {
                int r = wm * 32 + mi * 16 + (lane & 15);
                int kh = kk * 16 + (lane >> 4) * 8;
                ldm_x4(af[mi], sm_u32(&As[r][kh]));
            }
            unsigned bf[4][2];
#pragma unroll
            for (int nt = 0; nt < 2; nt++) {
                int g = lane >> 3, r = lane & 7;
                int krow = kk * 16 + (g & 1) * 8 + r;
                int ncol = wn * 32 + nt * 16 + (g >> 1) * 8;
                unsigned t[4];
                ldm_x4t(t, sm_u32(&Ws[krow][ncol]));
                bf[nt * 2 + 0][0] = t[0]; bf[nt * 2 + 0][1] = t[1];
                bf[nt * 2 + 1][0] = t[2]; bf[nt * 2 + 1][1] = t[3];
            }
#pragma unroll
            for (int mi = 0; mi < 2; mi++)
#pragma unroll
                for (int ni = 0; ni < 4; ni++)
                    mma16816(acc[mi][ni], af[mi], bf[ni]);
        }
    }

    const int r1 = lane >> 2;
    const int c2 = (lane & 3) * 2;
#pragma unroll
    for (int mi = 0; mi < 2; mi++) {
        int gr0 = row0 + wm * 32 + mi * 16 + r1;
        int gr1 = gr0 + 8;
        float d0 = (gr0 < n) ? g_dinv[gr0] : 0.f;
        float d1 = (gr1 < n) ? g_dinv[gr1] : 0.f;
        float dd0 = d0 * d0, dd1 = d1 * d1;
#pragma unroll
        for (int ni = 0; ni < 4; ni++) {
            int col = wn * 32 + ni * 8 + c2;
            if (col >= 40) continue;
            float bx = b[col], by = b[col + 1];
            float c0 = acc[mi][ni][0], c1 = acc[mi][ni][1];
            float c3 = acc[mi][ni][2], c4 = acc[mi][ni][3];
            if (gr0 < n) {
                __half2 h = __floats2half2_rn(c0 * d0, c1 * d0);
                *(unsigned*)(H2h + (size_t)gr0 * 40 + col) = *(unsigned*)&h;
                *(float2*)(OUT + (size_t)gr0 * 40 + col) =
                    make_float2(c0 * dd0 + bx, c1 * dd0 + by);
            }
            if (gr1 < n) {
                __half2 h = __floats2half2_rn(c3 * d1, c4 * d1);
                *(unsigned*)(H2h + (size_t)gr1 * 40 + col) = *(unsigned*)&h;
                *(float2*)(OUT + (size_t)gr1 * 40 + col) =
                    make_float2(c3 * dd1 + bx, c4 * dd1 + by);
            }
        }
    }
}

// ------------------------------------------------------------------
// SpMM aggregation (fp16 pre-scaled messages, fp32 AGG):
//   AGG[d] += dinv[d] * sum_{s in row d} Hh[s]
// ------------------------------------------------------------------
__global__ __launch_bounds__(256)
void k_spmm128(const __half* __restrict__ hh, float* __restrict__ agg, int n) {
    int w = (blockIdx.x * blockDim.x + threadIdx.x) >> 5;
    if (w >= n) return;
    int lane = threadIdx.x & 31;
    int beg = g_rowptr[w];
    int end = g_rowptr[w + 1];
    float dd = g_dinv[w];
    float4 acc = make_float4(0.f, 0.f, 0.f, 0.f);

    int idx = beg;
    for (; idx + 4 <= end; idx += 4) {
        int s0 = g_csr[idx + 0], s1 = g_csr[idx + 1];
        int s2 = g_csr[idx + 2], s3 = g_csr[idx + 3];
        uint2 u0 = *(const uint2*)(hh + (size_t)s0 * 128 + lane * 4);
        uint2 u1 = *(const uint2*)(hh + (size_t)s1 * 128 + lane * 4);
        uint2 u2 = *(const uint2*)(hh + (size_t)s2 * 128 + lane * 4);
        uint2 u3 = *(const uint2*)(hh + (size_t)s3 * 128 + lane * 4);
#pragma unroll
        for (int q = 0; q < 4; q++) {
            uint2 u = (q == 0) ? u0 : (q == 1) ? u1 : (q == 2) ? u2 : u3;
            float2 f0 = __half22float2(*(const __half2*)&u.x);
            float2 f1 = __half22float2(*(const __half2*)&u.y);
            acc.x += f0.x; acc.y += f0.y; acc.z += f1.x; acc.w += f1.y;
        }
    }
    for (; idx < end; ++idx) {
        int s = g_csr[idx];
        uint2 u = *(const uint2*)(hh + (size_t)s * 128 + lane * 4);
        float2 f0 = __half22float2(*(const __half2*)&u.x);
        float2 f1 = __half22float2(*(const __half2*)&u.y);
        acc.x += f0.x; acc.y += f0.y; acc.z += f1.x; acc.w += f1.y;
    }
    float* o = agg + (size_t)w * 128 + lane * 4;
    float4 cur = *(const float4*)o;
    cur.x += dd * acc.x; cur.y += dd * acc.y;
    cur.z += dd * acc.z; cur.w += dd * acc.w;
    *(float4*)o = cur;
}

__global__ __launch_bounds__(256)
void k_spmm40h(const __half* __restrict__ hh, float* __restrict__ out, int n) {
    int w = (blockIdx.x * blockDim.x + threadIdx.x) >> 5;
    if (w >= n) return;
    int lane = threadIdx.x & 31;
    if (lane >= 20) return;
    int beg = g_rowptr[w];
    int end = g_rowptr[w + 1];
    float dd = g_dinv[w];
    float2 acc = make_float2(0.f, 0.f);

    int idx = beg;
    for (; idx + 4 <= end; idx += 4) {
        int s0 = g_csr[idx + 0], s1 = g_csr[idx + 1];
        int s2 = g_csr[idx + 2], s3 = g_csr[idx + 3];
        unsigned u0 = *(const unsigned*)(hh + (size_t)s0 * 40 + lane * 2);
        unsigned u1 = *(const unsigned*)(hh + (size_t)s1 * 40 + lane * 2);
        unsigned u2 = *(const unsigned*)(hh + (size_t)s2 * 40 + lane * 2);
        unsigned u3 = *(const unsigned*)(hh + (size_t)s3 * 40 + lane * 2);
        float2 f0 = __half22float2(*(const __half2*)&u0);
        float2 f1 = __half22float2(*(const __half2*)&u1);
        float2 f2 = __half22float2(*(const __half2*)&u2);
        float2 f3 = __half22float2(*(const __half2*)&u3);
        acc.x += f0.x + f1.x + f2.x + f3.x;
        acc.y += f0.y + f1.y + f2.y + f3.y;
    }
    for (; idx < end; ++idx) {
        int s = g_csr[idx];
        unsigned u = *(const unsigned*)(hh + (size_t)s * 40 + lane * 2);
        float2 f = __half22float2(*(const __half2*)&u);
        acc.x += f.x; acc.y += f.y;
    }
    float* o = out + (size_t)w * 40 + lane * 2;
    float2 cur = *(const float2*)o;
    cur.x += dd * acc.x; cur.y += dd * acc.y;
    *(float2*)o = cur;
}

// ------------------------------------------------------------------
extern "C" void kernel_launch(void* const* d_in, const int* in_sizes, int n_in,
                              void* d_out, int out_size) {
    const float* x  = (const float*)d_in[0];
    const float* W0 = (const float*)d_in[1];
    const float* b0 = (const float*)d_in[2];
    const float* W1 = (const float*)d_in[3];
    const float* b1 = (const float*)d_in[4];
    const float* W2 = (const float*)d_in[5];
    const float* b2 = (const float*)d_in[6];
    const void*  ei = d_in[7];
    int n = in_sizes[0] / FEAT;
    int E = in_sizes[7] / 2;
    if (E > EMAX) E = EMAX;
    float* out = (float*)d_out;

    __half *pHh, *pH2h; float* pAGG;
    cudaGetSymbolAddress((void**)&pHh,  g_Hh);
    cudaGetSymbolAddress((void**)&pH2h, g_H2h);
    cudaGetSymbolAddress((void**)&pAGG, g_AGG);

    // one-time resources (no device memory involved)
    static cudaStream_t s2 = nullptr;
    static cudaEvent_t evFork = nullptr, evJoin = nullptr;
    static bool attrSet = false;
    if (!s2) {
        cudaStreamCreateWithFlags(&s2, cudaStreamNonBlocking);
        cudaEventCreateWithFlags(&evFork, cudaEventDisableTiming);
        cudaEventCreateWithFlags(&evJoin, cudaEventDisableTiming);
    }
    const int GSMEM = 2 * 17408 * (int)sizeof(__half);   // 69632 B
    if (!attrSet) {
        cudaFuncSetAttribute(k_gemm128h<false>,
                             cudaFuncAttributeMaxDynamicSharedMemorySize, GSMEM);
        cudaFuncSetAttribute(k_gemm128h<true>,
                             cudaFuncAttributeMaxDynamicSharedMemorySize, GSMEM);
        attrSet = true;
    }

    const int tb = 256;
    int nblk  = (n + tb - 1) / tb;
    int eblk  = (E + tb - 1) / tb;
    int gblk  = (n + 127) / 128;
    int scblk = (n + 1023) / 1024;
    int wblk  = (int)(((long long)n * 32 + tb - 1) / tb);

    // ---- degree + dinv (needed by GEMM epilogue) ----
    k_zero_deg<<<nblk, tb>>>(ei, n);
    k_count<<<eblk, tb>>>(ei, E);
    k_scanA<<<scblk, 1024>>>(n);

    // ---- fork: layer-0 GEMM on s2 || CSR finish on main ----
    cudaEventRecord(evFork, 0);
    cudaStreamWaitEvent(s2, evFork, 0);
    k_gemm128h<false><<<gblk, 256, GSMEM, s2>>>(x, W0, b0, pHh, pAGG, n);
    cudaEventRecord(evJoin, s2);

    k_scanB<<<1, 128>>>(scblk);
    k_scanC<<<scblk, 1024>>>(n, E);
    k_fill<<<eblk, tb>>>(ei, E);
    cudaStreamWaitEvent(0, evJoin, 0);

    // ---- join: rest of the pipeline serial on main ----
    k_spmm128<<<wblk, tb>>>(pHh, pAGG, n);
    k_gemm128h<true><<<gblk, 256, GSMEM>>>(pAGG, W1, b1, pHh, pAGG, n);
    k_spmm128<<<wblk, tb>>>(pHh, pAGG, n);
    k_gemm40h<<<gblk, 256>>>(pAGG, W2, b2, pH2h, out, n);
    k_spmm40h<<<wblk, tb>>>(pH2h, out, n);
}

// round 10
// speedup vs baseline: 1.4842x; 1.1020x over previous
#include <cuda_runtime.h>
#include <cuda_fp16.h>

#define NN    100000
#define FEAT  128
#define CLS   40
#define EMAX  1600000

// ---- scratch (static device globals; no allocation allowed) ----
__device__ int    g_degi[NN];
__device__ float  g_dinv[NN];
__device__ __half g_Hh[(size_t)NN * FEAT];   // pre-scaled fp16 messages h*dinv
__device__ float  g_AGG[(size_t)NN * FEAT];  // fp32 aggregation buffer
__device__ __half g_H2h[(size_t)NN * CLS];   // layer-2 pre-scaled fp16 messages
__device__ int    g_is64;                    // edge_index dtype flag
__device__ int    g_rowptr[NN + 1];
__device__ int    g_cursor[NN];
__device__ int    g_csr[EMAX];               // src ids grouped by dst
__device__ int    g_bsum[128];
__device__ int    g_boff[128];

// ---- mma helpers ----
__device__ __forceinline__ unsigned sm_u32(const void* p) {
    return (unsigned)__cvta_generic_to_shared(p);
}
__device__ __forceinline__ void ldm_x4(unsigned* r, unsigned a) {
    asm volatile("ldmatrix.sync.aligned.m8n8.x4.shared.b16 {%0,%1,%2,%3}, [%4];"
                 : "=r"(r[0]), "=r"(r[1]), "=r"(r[2]), "=r"(r[3]) : "r"(a));
}
__device__ __forceinline__ void ldm_x4t(unsigned* r, unsigned a) {
    asm volatile("ldmatrix.sync.aligned.m8n8.x4.trans.shared.b16 {%0,%1,%2,%3}, [%4];"
                 : "=r"(r[0]), "=r"(r[1]), "=r"(r[2]), "=r"(r[3]) : "r"(a));
}
__device__ __forceinline__ void mma16816(float* d, const unsigned* a,
                                         const unsigned* b) {
    asm volatile(
        "mma.sync.aligned.m16n8k16.row.col.f32.f16.f16.f32 "
        "{%0,%1,%2,%3},{%4,%5,%6,%7},{%8,%9},{%0,%1,%2,%3};"
        : "+f"(d[0]), "+f"(d[1]), "+f"(d[2]), "+f"(d[3])
        : "r"(a[0]), "r"(a[1]), "r"(a[2]), "r"(a[3]), "r"(b[0]), "r"(b[1]));
}

// ------------------------------------------------------------------
// degree / dinv / CSR build
// ------------------------------------------------------------------
__global__ void k_zero_deg(const void* ei, int n) {
    int i = blockIdx.x * blockDim.x + threadIdx.x;
    if (i < n) g_degi[i] = 0;
    if (i == 0) {
        const unsigned long long* p = (const unsigned long long*)ei;
        g_is64 = (p[0] < (unsigned long long)n && p[1] < (unsigned long long)n) ? 1 : 0;
    }
}

__global__ void k_count(const void* ei, int E) {
    int e = blockIdx.x * blockDim.x + threadIdx.x;
    if (e >= E) return;
    int dst;
    if (g_is64) dst = (int)((const long long*)ei)[E + e];
    else        dst = ((const int*)ei)[E + e];
    atomicAdd(&g_degi[dst], 1);
}

// scanA also produces dinv (fused)
__global__ void k_scanA(int n) {
    __shared__ int s[1024];
    int i = blockIdx.x * 1024 + threadIdx.x;
    int v = (i < n) ? g_degi[i] : 0;
    if (i < n) g_dinv[i] = rsqrtf((float)v + 1.f);
    s[threadIdx.x] = v;
    __syncthreads();
#pragma unroll
    for (int off = 1; off < 1024; off <<= 1) {
        int x = (threadIdx.x >= off) ? s[threadIdx.x - off] : 0;
        __syncthreads();
        s[threadIdx.x] += x;
        __syncthreads();
    }
    if (i < n) g_rowptr[i] = s[threadIdx.x] - v;
    if (threadIdx.x == 1023) g_bsum[blockIdx.x] = s[1023];
}

__global__ void k_scanB(int nb) {
    __shared__ int s[128];
    int t = threadIdx.x;
    int v = (t < nb) ? g_bsum[t] : 0;
    s[t] = v;
    __syncthreads();
#pragma unroll
    for (int off = 1; off < 128; off <<= 1) {
        int x = (t >= off) ? s[t - off] : 0;
        __syncthreads();
        s[t] += x;
        __syncthreads();
    }
    g_boff[t] = s[t] - v;
}

__global__ void k_scanC(int n, int E) {
    int i = blockIdx.x * 1024 + threadIdx.x;
    if (i < n) {
        int r = g_rowptr[i] + g_boff[blockIdx.x];
        g_rowptr[i] = r;
        g_cursor[i] = r;
    }
    if (i == 0) g_rowptr[n] = E;
}

__global__ void k_fill(const void* ei, int E) {
    int e = blockIdx.x * blockDim.x + threadIdx.x;
    if (e >= E) return;
    int s, d;
    if (g_is64) {
        const long long* p = (const long long*)ei;
        s = (int)p[e]; d = (int)p[E + e];
    } else {
        const int* p = (const int*)ei;
        s = p[e]; d = p[E + e];
    }
    int pos = atomicAdd(&g_cursor[d], 1);
    g_csr[pos] = s;
}

// ------------------------------------------------------------------
// Tensor-core GEMM (K=128, Nout=128), SINGLE-SHOT smem:
//   h  = act(A) @ W   (fp16 in, fp32 acc)
//   Hh = half(h * dinv)   -- ONLY output (self-loop folded into spmm)
// ------------------------------------------------------------------
#define SPITCH 136
#define AS(r, c) dsm[(r) * SPITCH + (c)]
#define WS(r, c) dsm[17408 + (r) * SPITCH + (c)]
#define HS(r, c) dsm[(r) * SPITCH + (c)]

template <bool RELU>
__global__ __launch_bounds__(256)
void k_gemm128h(const float* __restrict__ A, const float* __restrict__ W,
                __half* __restrict__ Hh, int n) {
    extern __shared__ __half dsm[];
    const int tid  = threadIdx.x;
    const int lane = tid & 31;
    const int warp = tid >> 5;
    const int wm   = warp & 3;
    const int wn   = warp >> 2;
    const int row0 = blockIdx.x * 128;

    float acc[2][8][4];
#pragma unroll
    for (int mi = 0; mi < 2; mi++)
#pragma unroll
        for (int ni = 0; ni < 8; ni++)
#pragma unroll
            for (int q = 0; q < 4; q++) acc[mi][ni][q] = 0.f;

    const int ar = tid >> 1, ac = (tid & 1) * 64;
    {
        int gr = row0 + ar;
        const float* Arow = A + (size_t)gr * 128 + ac;
#pragma unroll
        for (int u = 0; u < 8; u++) {
            float4 f0 = make_float4(0.f, 0.f, 0.f, 0.f), f1 = f0;
            if (gr < n) {
                f0 = *(const float4*)(Arow + u * 8);
                f1 = *(const float4*)(Arow + u * 8 + 4);
            }
            if (RELU) {
                f0.x = fmaxf(f0.x, 0.f); f0.y = fmaxf(f0.y, 0.f);
                f0.z = fmaxf(f0.z, 0.f); f0.w = fmaxf(f0.w, 0.f);
                f1.x = fmaxf(f1.x, 0.f); f1.y = fmaxf(f1.y, 0.f);
                f1.z = fmaxf(f1.z, 0.f); f1.w = fmaxf(f1.w, 0.f);
            }
            __half2 hh[4];
            hh[0] = __floats2half2_rn(f0.x, f0.y);
            hh[1] = __floats2half2_rn(f0.z, f0.w);
            hh[2] = __floats2half2_rn(f1.x, f1.y);
            hh[3] = __floats2half2_rn(f1.z, f1.w);
            *(uint4*)&AS(ar, ac + u * 8) = *(uint4*)hh;
        }
    }
    {
        const float* Wrow = W + (size_t)ar * 128 + ac;
#pragma unroll
        for (int u = 0; u < 8; u++) {
            float4 f0 = *(const float4*)(Wrow + u * 8);
            float4 f1 = *(const float4*)(Wrow + u * 8 + 4);
            __half2 hh[4];
            hh[0] = __floats2half2_rn(f0.x, f0.y);
            hh[1] = __floats2half2_rn(f0.z, f0.w);
            hh[2] = __floats2half2_rn(f1.x, f1.y);
            hh[3] = __floats2half2_rn(f1.z, f1.w);
            *(uint4*)&WS(ar, ac + u * 8) = *(uint4*)hh;
        }
    }
    __syncthreads();

#pragma unroll
    for (int kk = 0; kk < 8; kk++) {
        unsigned af[2][4];
#pragma unroll
        for (int mi = 0; mi < 2; mi++) {
            int r = wm * 32 + mi * 16 + (lane & 15);
            int kh = kk * 16 + (lane >> 4) * 8;
            ldm_x4(af[mi], sm_u32(&AS(r, kh)));
        }
        unsigned bf[8][2];
#pragma unroll
        for (int nt = 0; nt < 4; nt++) {
            int g = lane >> 3, r = lane & 7;
            int krow = kk * 16 + (g & 1) * 8 + r;
            int ncol = wn * 64 + nt * 16 + (g >> 1) * 8;
            unsigned t[4];
            ldm_x4t(t, sm_u32(&WS(krow, ncol)));
            bf[nt * 2 + 0][0] = t[0]; bf[nt * 2 + 0][1] = t[1];
            bf[nt * 2 + 1][0] = t[2]; bf[nt * 2 + 1][1] = t[3];
        }
#pragma unroll
        for (int mi = 0; mi < 2; mi++)
#pragma unroll
            for (int ni = 0; ni < 8; ni++)
                mma16816(acc[mi][ni], af[mi], bf[ni]);
    }

    // epilogue: stage h into smem, one coalesced Hh store pass
    __syncthreads();
    {
        const int r1 = lane >> 2;
        const int c2 = (lane & 3) * 2;
#pragma unroll
        for (int mi = 0; mi < 2; mi++) {
            int r = wm * 32 + mi * 16 + r1;
#pragma unroll
            for (int ni = 0; ni < 8; ni++) {
                int col = wn * 64 + ni * 8 + c2;
                __half2 h01 = __floats2half2_rn(acc[mi][ni][0], acc[mi][ni][1]);
                __half2 h23 = __floats2half2_rn(acc[mi][ni][2], acc[mi][ni][3]);
                *(__half2*)&HS(r, col)     = h01;
                *(__half2*)&HS(r + 8, col) = h23;
            }
        }
    }
    __syncthreads();
    {
        int rrow  = tid >> 4;
        int chunk = tid & 15;
#pragma unroll
        for (int p = 0; p < 8; p++) {
            int r = p * 16 + rrow;
            int gr = row0 + r;
            if (gr < n) {
                __half2 d2 = __float2half2_rn(g_dinv[gr]);
                uint4 u = *(uint4*)&HS(r, chunk * 8);
                __half2* hp = (__half2*)&u;
                hp[0] = __hmul2(hp[0], d2); hp[1] = __hmul2(hp[1], d2);
                hp[2] = __hmul2(hp[2], d2); hp[3] = __hmul2(hp[3], d2);
                *(uint4*)(Hh + (size_t)gr * 128 + chunk * 8) = u;
            }
        }
    }
}

// ------------------------------------------------------------------
// Tensor-core GEMM (K=128, Nout=40 padded to 64), fp32 A:
//   h2 = relu(A) @ W2 ; H2h = half(h2*dinv)   -- ONLY output
// ------------------------------------------------------------------
__global__ __launch_bounds__(256, 2)
void k_gemm40h(const float* __restrict__ A, const float* __restrict__ W,
               __half* __restrict__ H2h, int n) {
    __shared__ __half As[128][72];
    __shared__ __half Ws[64][72];
    const int tid  = threadIdx.x;
    const int lane = tid & 31;
    const int warp = tid >> 5;
    const int wm   = warp & 3;
    const int wn   = warp >> 2;
    const int row0 = blockIdx.x * 128;

    float acc[2][4][4];
#pragma unroll
    for (int mi = 0; mi < 2; mi++)
#pragma unroll
        for (int ni = 0; ni < 4; ni++)
#pragma unroll
            for (int q = 0; q < 4; q++) acc[mi][ni][q] = 0.f;

    const int ar = tid >> 1, ac = (tid & 1) * 32;

#pragma unroll
    for (int kb = 0; kb < 2; kb++) {
        if (kb) __syncthreads();
        {
            int gr = row0 + ar;
            const float* Arow = A + (size_t)gr * 128 + kb * 64 + ac;
#pragma unroll
            for (int u = 0; u < 4; u++) {
                float4 f0 = make_float4(0.f, 0.f, 0.f, 0.f), f1 = f0;
                if (gr < n) {
                    f0 = *(const float4*)(Arow + u * 8);
                    f1 = *(const float4*)(Arow + u * 8 + 4);
                }
                f0.x = fmaxf(f0.x, 0.f); f0.y = fmaxf(f0.y, 0.f);
                f0.z = fmaxf(f0.z, 0.f); f0.w = fmaxf(f0.w, 0.f);
                f1.x = fmaxf(f1.x, 0.f); f1.y = fmaxf(f1.y, 0.f);
                f1.z = fmaxf(f1.z, 0.f); f1.w = fmaxf(f1.w, 0.f);
                __half2 hh[4];
                hh[0] = __floats2half2_rn(f0.x, f0.y);
                hh[1] = __floats2half2_rn(f0.z, f0.w);
                hh[2] = __floats2half2_rn(f1.x, f1.y);
                hh[3] = __floats2half2_rn(f1.z, f1.w);
                *(uint4*)&As[ar][ac + u * 8] = *(uint4*)hh;
            }
        }
        for (int idx = tid; idx < 64 * 64; idx += 256) {
            int k = idx >> 6, c = idx & 63;
            float v = (c < 40) ? W[(size_t)(kb * 64 + k) * 40 + c] : 0.f;
            Ws[k][c] = __float2half_rn(v);
        }
        __syncthreads();

#pragma unroll
        for (int kk = 0; kk < 4; kk++) {
            unsigned af[2][4];
#pragma unroll
            for (int mi = 0; mi < 2; mi++) {
                int r = wm * 32 + mi * 16 + (lane & 15);
                int kh = kk * 16 + (lane >> 4) * 8;
                ldm_x4(af[mi], sm_u32(&As[r][kh]));
            }
            unsigned bf[4][2];
#pragma unroll
            for (int nt = 0; nt < 2; nt++) {
                int g = lane >> 3, r = lane & 7;
                int krow = kk * 16 + (g & 1) * 8 + r;
                int ncol = wn * 32 + nt * 16 + (g >> 1) * 8;
                unsigned t[4];
                ldm_x4t(t, sm_u32(&Ws[krow][ncol]));
                bf[nt * 2 + 0][0] = t[0]; bf[nt * 2 + 0][1] = t[1];
                bf[nt * 2 + 1][0] = t[2]; bf[nt * 2 + 1][1] = t[3];
            }
#pragma unroll
            for (int mi = 0; mi < 2; mi++)
#pragma unroll
                for (int ni = 0; ni < 4; ni++)
                    mma16816(acc[mi][ni], af[mi], bf[ni]);
        }
    }

    const int r1 = lane >> 2;
    const int c2 = (lane & 3) * 2;
#pragma unroll
    for (int mi = 0; mi < 2; mi++) {
        int gr0 = row0 + wm * 32 + mi * 16 + r1;
        int gr1 = gr0 + 8;
        float d0 = (gr0 < n) ? g_dinv[gr0] : 0.f;
        float d1 = (gr1 < n) ? g_dinv[gr1] : 0.f;
#pragma unroll
        for (int ni = 0; ni < 4; ni++) {
            int col = wn * 32 + ni * 8 + c2;
            if (col >= 40) continue;
            if (gr0 < n) {
                __half2 h = __floats2half2_rn(acc[mi][ni][0] * d0,
                                              acc[mi][ni][1] * d0);
                *(unsigned*)(H2h + (size_t)gr0 * 40 + col) = *(unsigned*)&h;
            }
            if (gr1 < n) {
                __half2 h = __floats2half2_rn(acc[mi][ni][2] * d1,
                                              acc[mi][ni][3] * d1);
                *(unsigned*)(H2h + (size_t)gr1 * 40 + col) = *(unsigned*)&h;
            }
        }
    }
}

// ------------------------------------------------------------------
// SpMM aggregation (fp16 messages; self-loop + bias folded in):
//   AGG[d] = dinv[d] * (Hh[d] + sum_{s in row d} Hh[s]) + b
// ------------------------------------------------------------------
__global__ __launch_bounds__(256)
void k_spmm128(const __half* __restrict__ hh, float* __restrict__ agg,
               const float* __restrict__ b, int n) {
    int w = (blockIdx.x * blockDim.x + threadIdx.x) >> 5;
    if (w >= n) return;
    int lane = threadIdx.x & 31;
    int beg = g_rowptr[w];
    int end = g_rowptr[w + 1];
    float dd = g_dinv[w];
    // self-loop init: acc = Hh[w]
    uint2 us = *(const uint2*)(hh + (size_t)w * 128 + lane * 4);
    float2 s0 = __half22float2(*(const __half2*)&us.x);
    float2 s1 = __half22float2(*(const __half2*)&us.y);
    float4 acc = make_float4(s0.x, s0.y, s1.x, s1.y);

    int idx = beg;
    for (; idx + 4 <= end; idx += 4) {
        int i0 = g_csr[idx + 0], i1 = g_csr[idx + 1];
        int i2 = g_csr[idx + 2], i3 = g_csr[idx + 3];
        uint2 u0 = *(const uint2*)(hh + (size_t)i0 * 128 + lane * 4);
        uint2 u1 = *(const uint2*)(hh + (size_t)i1 * 128 + lane * 4);
        uint2 u2 = *(const uint2*)(hh + (size_t)i2 * 128 + lane * 4);
        uint2 u3 = *(const uint2*)(hh + (size_t)i3 * 128 + lane * 4);
#pragma unroll
        for (int q = 0; q < 4; q++) {
            uint2 u = (q == 0) ? u0 : (q == 1) ? u1 : (q == 2) ? u2 : u3;
            float2 f0 = __half22float2(*(const __half2*)&u.x);
            float2 f1 = __half22float2(*(const __half2*)&u.y);
            acc.x += f0.x; acc.y += f0.y; acc.z += f1.x; acc.w += f1.y;
        }
    }
    for (; idx < end; ++idx) {
        int s = g_csr[idx];
        uint2 u = *(const uint2*)(hh + (size_t)s * 128 + lane * 4);
        float2 f0 = __half22float2(*(const __half2*)&u.x);
        float2 f1 = __half22float2(*(const __half2*)&u.y);
        acc.x += f0.x; acc.y += f0.y; acc.z += f1.x; acc.w += f1.y;
    }
    float4 bv = *(const float4*)(b + lane * 4);
    float4 res = make_float4(dd * acc.x + bv.x, dd * acc.y + bv.y,
                             dd * acc.z + bv.z, dd * acc.w + bv.w);
    *(float4*)(agg + (size_t)w * 128 + lane * 4) = res;
}

// layer-2: OUT[d] = dinv[d] * (H2h[d] + sum Hh2[s]) + b2  (fp32 out)
__global__ __launch_bounds__(256)
void k_spmm40h(const __half* __restrict__ hh, float* __restrict__ out,
               const float* __restrict__ b, int n) {
    int w = (blockIdx.x * blockDim.x + threadIdx.x) >> 5;
    if (w >= n) return;
    int lane = threadIdx.x & 31;
    if (lane >= 20) return;
    int beg = g_rowptr[w];
    int end = g_rowptr[w + 1];
    float dd = g_dinv[w];
    unsigned usf = *(const unsigned*)(hh + (size_t)w * 40 + lane * 2);
    float2 acc = __half22float2(*(const __half2*)&usf);

    int idx = beg;
    for (; idx + 4 <= end; idx += 4) {
        int i0 = g_csr[idx + 0], i1 = g_csr[idx + 1];
        int i2 = g_csr[idx + 2], i3 = g_csr[idx + 3];
        unsigned u0 = *(const unsigned*)(hh + (size_t)i0 * 40 + lane * 2);
        unsigned u1 = *(const unsigned*)(hh + (size_t)i1 * 40 + lane * 2);
        unsigned u2 = *(const unsigned*)(hh + (size_t)i2 * 40 + lane * 2);
        unsigned u3 = *(const unsigned*)(hh + (size_t)i3 * 40 + lane * 2);
        float2 f0 = __half22float2(*(const __half2*)&u0);
        float2 f1 = __half22float2(*(const __half2*)&u1);
        float2 f2 = __half22float2(*(const __half2*)&u2);
        float2 f3 = __half22float2(*(const __half2*)&u3);
        acc.x += f0.x + f1.x + f2.x + f3.x;
        acc.y += f0.y + f1.y + f2.y + f3.y;
    }
    for (; idx < end; ++idx) {
        int s = g_csr[idx];
        unsigned u = *(const unsigned*)(hh + (size_t)s * 40 + lane * 2);
        float2 f = __half22float2(*(const __half2*)&u);
        acc.x += f.x; acc.y += f.y;
    }
    float2 bv = *(const float2*)(b + lane * 2);
    float2 res = make_float2(dd * acc.x + bv.x, dd * acc.y + bv.y);
    *(float2*)(out + (size_t)w * 40 + lane * 2) = res;
}

// ------------------------------------------------------------------
extern "C" void kernel_launch(void* const* d_in, const int* in_sizes, int n_in,
                              void* d_out, int out_size) {
    const float* x  = (const float*)d_in[0];
    const float* W0 = (const float*)d_in[1];
    const float* b0 = (const float*)d_in[2];
    const float* W1 = (const float*)d_in[3];
    const float* b1 = (const float*)d_in[4];
    const float* W2 = (const float*)d_in[5];
    const float* b2 = (const float*)d_in[6];
    const void*  ei = d_in[7];
    int n = in_sizes[0] / FEAT;
    int E = in_sizes[7] / 2;
    if (E > EMAX) E = EMAX;
    float* out = (float*)d_out;

    __half *pHh, *pH2h; float* pAGG;
    cudaGetSymbolAddress((void**)&pHh,  g_Hh);
    cudaGetSymbolAddress((void**)&pH2h, g_H2h);
    cudaGetSymbolAddress((void**)&pAGG, g_AGG);

    static cudaStream_t s2 = nullptr;
    static cudaEvent_t evFork = nullptr, evJoin = nullptr;
    static bool attrSet = false;
    if (!s2) {
        cudaStreamCreateWithFlags(&s2, cudaStreamNonBlocking);
        cudaEventCreateWithFlags(&evFork, cudaEventDisableTiming);
        cudaEventCreateWithFlags(&evJoin, cudaEventDisableTiming);
    }
    const int GSMEM = 2 * 17408 * (int)sizeof(__half);   // 69632 B
    if (!attrSet) {
        cudaFuncSetAttribute(k_gemm128h<false>,
                             cudaFuncAttributeMaxDynamicSharedMemorySize, GSMEM);
        cudaFuncSetAttribute(k_gemm128h<true>,
                             cudaFuncAttributeMaxDynamicSharedMemorySize, GSMEM);
        attrSet = true;
    }

    const int tb = 256;
    int nblk  = (n + tb - 1) / tb;
    int eblk  = (E + tb - 1) / tb;
    int gblk  = (n + 127) / 128;
    int scblk = (n + 1023) / 1024;
    int wblk  = (int)(((long long)n * 32 + tb - 1) / tb);

    // ---- degree + dinv ----
    k_zero_deg<<<nblk, tb>>>(ei, n);
    k_count<<<eblk, tb>>>(ei, E);
    k_scanA<<<scblk, 1024>>>(n);

    // ---- fork: layer-0 GEMM on s2 || CSR finish on main ----
    cudaEventRecord(evFork, 0);
    cudaStreamWaitEvent(s2, evFork, 0);
    k_gemm128h<false><<<gblk, 256, GSMEM, s2>>>(x, W0, pHh, n);
    cudaEventRecord(evJoin, s2);

    k_scanB<<<1, 128>>>(scblk);
    k_scanC<<<scblk, 1024>>>(n, E);
    k_fill<<<eblk, tb>>>(ei, E);
    cudaStreamWaitEvent(0, evJoin, 0);

    // ---- join: rest of the pipeline ----
    k_spmm128<<<wblk, tb>>>(pHh, pAGG, b0, n);
    k_gemm128h<true><<<gblk, 256, GSMEM>>>(pAGG, W1, pHh, n);
    k_spmm128<<<wblk, tb>>>(pHh, pAGG, b1, n);
    k_gemm40h<<<gblk, 256>>>(pAGG, W2, pH2h, n);
    k_spmm40h<<<wblk, tb>>>(pH2h, out, b2, n);
}

// round 11
// speedup vs baseline: 1.7348x; 1.1689x over previous
#include <cuda_runtime.h>
#include <cuda_fp16.h>

#define NN    100000
#define FEAT  128
#define CLS   40
#define EMAX  1600000

// ---- scratch (static device globals; no allocation allowed) ----
__device__ int    g_degi[NN];
__device__ float  g_dinv[NN];
__device__ __half g_Hh[(size_t)NN * FEAT];   // pre-scaled fp16 messages h*dinv
__device__ __half g_AGG[(size_t)NN * FEAT];  // fp16 relu'd conv output
__device__ __half g_H2h[(size_t)NN * CLS];   // layer-2 pre-scaled fp16 messages
__device__ __half g_W0h[16384];
__device__ __half g_W1h[16384];
__device__ __half g_W2p[128 * 64];           // W2 padded 40->64 cols
__device__ int    g_is64;
__device__ int    g_rowptr[NN + 1];
__device__ int    g_cursor[NN];
__device__ int    g_csr[EMAX];
__device__ int    g_bsum[128];
__device__ int    g_boff[128];

// ---- helpers ----
__device__ __forceinline__ unsigned sm_u32(const void* p) {
    return (unsigned)__cvta_generic_to_shared(p);
}
__device__ __forceinline__ void ldm_x4(unsigned* r, unsigned a) {
    asm volatile("ldmatrix.sync.aligned.m8n8.x4.shared.b16 {%0,%1,%2,%3}, [%4];"
                 : "=r"(r[0]), "=r"(r[1]), "=r"(r[2]), "=r"(r[3]) : "r"(a));
}
__device__ __forceinline__ void ldm_x4t(unsigned* r, unsigned a) {
    asm volatile("ldmatrix.sync.aligned.m8n8.x4.trans.shared.b16 {%0,%1,%2,%3}, [%4];"
                 : "=r"(r[0]), "=r"(r[1]), "=r"(r[2]), "=r"(r[3]) : "r"(a));
}
__device__ __forceinline__ void mma16816(float* d, const unsigned* a,
                                         const unsigned* b) {
    asm volatile(
        "mma.sync.aligned.m16n8k16.row.col.f32.f16.f16.f32 "
        "{%0,%1,%2,%3},{%4,%5,%6,%7},{%8,%9},{%0,%1,%2,%3};"
        : "+f"(d[0]), "+f"(d[1]), "+f"(d[2]), "+f"(d[3])
        : "r"(a[0]), "r"(a[1]), "r"(a[2]), "r"(a[3]), "r"(b[0]), "r"(b[1]));
}
__device__ __forceinline__ void cp16(unsigned d, const void* s) {
    asm volatile("cp.async.ca.shared.global [%0], [%1], 16;" :: "r"(d), "l"(s));
}
__device__ __forceinline__ void cp16p(unsigned d, const void* s, bool p) {
    int sz = p ? 16 : 0;
    asm volatile("cp.async.ca.shared.global [%0], [%1], 16, %2;"
                 :: "r"(d), "l"(s), "r"(sz));
}
__device__ __forceinline__ void cp_wait() {
    asm volatile("cp.async.commit_group;" ::: "memory");
    asm volatile("cp.async.wait_group 0;" ::: "memory");
}

// ------------------------------------------------------------------
// degree / dinv / CSR build
// ------------------------------------------------------------------
__global__ void k_zero_deg(const void* ei, int n) {
    int i = blockIdx.x * blockDim.x + threadIdx.x;
    if (i < n) g_degi[i] = 0;
    if (i == 0) {
        const unsigned long long* p = (const unsigned long long*)ei;
        g_is64 = (p[0] < (unsigned long long)n && p[1] < (unsigned long long)n) ? 1 : 0;
    }
}

__global__ void k_count(const void* ei, int E) {
    int e = blockIdx.x * blockDim.x + threadIdx.x;
    if (e >= E) return;
    int dst;
    if (g_is64) dst = (int)((const long long*)ei)[E + e];
    else        dst = ((const int*)ei)[E + e];
    atomicAdd(&g_degi[dst], 1);
}

__global__ void k_scanA(int n) {
    __shared__ int s[1024];
    int i = blockIdx.x * 1024 + threadIdx.x;
    int v = (i < n) ? g_degi[i] : 0;
    if (i < n) g_dinv[i] = rsqrtf((float)v + 1.f);
    s[threadIdx.x] = v;
    __syncthreads();
#pragma unroll
    for (int off = 1; off < 1024; off <<= 1) {
        int x = (threadIdx.x >= off) ? s[threadIdx.x - off] : 0;
        __syncthreads();
        s[threadIdx.x] += x;
        __syncthreads();
    }
    if (i < n) g_rowptr[i] = s[threadIdx.x] - v;
    if (threadIdx.x == 1023) g_bsum[blockIdx.x] = s[1023];
}

__global__ void k_scanB(int nb) {
    __shared__ int s[128];
    int t = threadIdx.x;
    int v = (t < nb) ? g_bsum[t] : 0;
    s[t] = v;
    __syncthreads();
#pragma unroll
    for (int off = 1; off < 128; off <<= 1) {
        int x = (t >= off) ? s[t - off] : 0;
        __syncthreads();
        s[t] += x;
        __syncthreads();
    }
    g_boff[t] = s[t] - v;
}

__global__ void k_scanC(int n, int E) {
    int i = blockIdx.x * 1024 + threadIdx.x;
    if (i < n) {
        int r = g_rowptr[i] + g_boff[blockIdx.x];
        g_rowptr[i] = r;
        g_cursor[i] = r;
    }
    if (i == 0) g_rowptr[n] = E;
}

__global__ void k_fill(const void* ei, int E) {
    int e = blockIdx.x * blockDim.x + threadIdx.x;
    if (e >= E) return;
    int s, d;
    if (g_is64) {
        const long long* p = (const long long*)ei;
        s = (int)p[e]; d = (int)p[E + e];
    } else {
        const int* p = (const int*)ei;
        s = p[e]; d = p[E + e];
    }
    int pos = atomicAdd(&g_cursor[d], 1);
    g_csr[pos] = s;
}

// weights -> fp16 (W2 padded 40->64)
__global__ void k_convW(const float* W0, const float* W1, const float* W2) {
    int i = blockIdx.x * blockDim.x + threadIdx.x;
    if (i < 16384) {
        g_W0h[i] = __float2half_rn(W0[i]);
    } else if (i < 32768) {
        g_W1h[i - 16384] = __float2half_rn(W1[i - 16384]);
    } else if (i < 32768 + 128 * 64) {
        int j = i - 32768;
        int k = j >> 6, c = j & 63;
        g_W2p[j] = __float2half_rn(c < 40 ? W2[k * 40 + c] : 0.f);
    }
}

// ------------------------------------------------------------------
// Tensor-core GEMM (K=128, Nout=128), single-shot smem, fp16 W:
//   h  = A @ Wh ; Hh = half(h * dinv)
// HIN: A fp16 (cp.async copy) else fp32 (convert path)
// ------------------------------------------------------------------
#define SPITCH 136
#define AS(r, c) dsm[(r) * SPITCH + (c)]
#define WS(r, c) dsm[17408 + (r) * SPITCH + (c)]
#define HS(r, c) dsm[(r) * SPITCH + (c)]

template <bool HIN>
__global__ __launch_bounds__(256)
void k_gemm128h(const void* __restrict__ A, const __half* __restrict__ Wh,
                __half* __restrict__ Hh, int n) {
    extern __shared__ __half dsm[];
    const int tid  = threadIdx.x;
    const int lane = tid & 31;
    const int warp = tid >> 5;
    const int wm   = warp & 3;
    const int wn   = warp >> 2;
    const int row0 = blockIdx.x * 128;

    float acc[2][8][4];
#pragma unroll
    for (int mi = 0; mi < 2; mi++)
#pragma unroll
        for (int ni = 0; ni < 8; ni++)
#pragma unroll
            for (int q = 0; q < 4; q++) acc[mi][ni][q] = 0.f;

    const int ar = tid >> 1, ac = (tid & 1) * 64;
    // W tile: fp16, pure cp.async copy
    {
        const __half* Wrow = Wh + ar * 128 + ac;
#pragma unroll
        for (int u = 0; u < 8; u++)
            cp16(sm_u32(&WS(ar, ac + u * 8)), Wrow + u * 8);
    }
    if (HIN) {
        int gr = row0 + ar;
        bool ok = gr < n;
        const __half* Arow = (const __half*)A + (size_t)gr * 128 + ac;
#pragma unroll
        for (int u = 0; u < 8; u++)
            cp16p(sm_u32(&AS(ar, ac + u * 8)), Arow + u * 8, ok);
    } else {
        int gr = row0 + ar;
        const float* Arow = (const float*)A + (size_t)gr * 128 + ac;
#pragma unroll
        for (int u = 0; u < 8; u++) {
            float4 f0 = make_float4(0.f, 0.f, 0.f, 0.f), f1 = f0;
            if (gr < n) {
                f0 = *(const float4*)(Arow + u * 8);
                f1 = *(const float4*)(Arow + u * 8 + 4);
            }
            __half2 hh[4];
            hh[0] = __floats2half2_rn(f0.x, f0.y);
            hh[1] = __floats2half2_rn(f0.z, f0.w);
            hh[2] = __floats2half2_rn(f1.x, f1.y);
            hh[3] = __floats2half2_rn(f1.z, f1.w);
            *(uint4*)&AS(ar, ac + u * 8) = *(uint4*)hh;
        }
    }
    cp_wait();
    __syncthreads();

#pragma unroll
    for (int kk = 0; kk < 8; kk++) {
        unsigned af[2][4];
#pragma unroll
        for (int mi = 0; mi < 2; mi++) {
            int r = wm * 32 + mi * 16 + (lane & 15);
            int kh = kk * 16 + (lane >> 4) * 8;
            ldm_x4(af[mi], sm_u32(&AS(r, kh)));
        }
        unsigned bf[8][2];
#pragma unroll
        for (int nt = 0; nt < 4; nt++) {
            int g = lane >> 3, r = lane & 7;
            int krow = kk * 16 + (g & 1) * 8 + r;
            int ncol = wn * 64 + nt * 16 + (g >> 1) * 8;
            unsigned t[4];
            ldm_x4t(t, sm_u32(&WS(krow, ncol)));
            bf[nt * 2 + 0][0] = t[0]; bf[nt * 2 + 0][1] = t[1];
            bf[nt * 2 + 1][0] = t[2]; bf[nt * 2 + 1][1] = t[3];
        }
#pragma unroll
        for (int mi = 0; mi < 2; mi++)
#pragma unroll
            for (int ni = 0; ni < 8; ni++)
                mma16816(acc[mi][ni], af[mi], bf[ni]);
    }

    // epilogue: stage h into smem, one coalesced Hh store pass
    __syncthreads();
    {
        const int r1 = lane >> 2;
        const int c2 = (lane & 3) * 2;
#pragma unroll
        for (int mi = 0; mi < 2; mi++) {
            int r = wm * 32 + mi * 16 + r1;
#pragma unroll
            for (int ni = 0; ni < 8; ni++) {
                int col = wn * 64 + ni * 8 + c2;
                __half2 h01 = __floats2half2_rn(acc[mi][ni][0], acc[mi][ni][1]);
                __half2 h23 = __floats2half2_rn(acc[mi][ni][2], acc[mi][ni][3]);
                *(__half2*)&HS(r, col)     = h01;
                *(__half2*)&HS(r + 8, col) = h23;
            }
        }
    }
    __syncthreads();
    {
        int rrow  = tid >> 4;
        int chunk = tid & 15;
#pragma unroll
        for (int p = 0; p < 8; p++) {
            int r = p * 16 + rrow;
            int gr = row0 + r;
            if (gr < n) {
                __half2 d2 = __float2half2_rn(g_dinv[gr]);
                uint4 u = *(uint4*)&HS(r, chunk * 8);
                __half2* hp = (__half2*)&u;
                hp[0] = __hmul2(hp[0], d2); hp[1] = __hmul2(hp[1], d2);
                hp[2] = __hmul2(hp[2], d2); hp[3] = __hmul2(hp[3], d2);
                *(uint4*)(Hh + (size_t)gr * 128 + chunk * 8) = u;
            }
        }
    }
}

// ------------------------------------------------------------------
// Tensor-core GEMM (K=128, Nout=64 padded; 40 real), fp16 A + W:
//   h2 = A @ W2p ; H2h = half(h2 * dinv)
// single-shot smem: As 128x136 + Ws 128x72 halves = 53248 B
// ------------------------------------------------------------------
#define WS40(r, c) dsm[17408 + (r) * 72 + (c)]

__global__ __launch_bounds__(256)
void k_gemm40h(const __half* __restrict__ A, __half* __restrict__ H2h, int n) {
    extern __shared__ __half dsm[];
    const int tid  = threadIdx.x;
    const int lane = tid & 31;
    const int warp = tid >> 5;
    const int wm   = warp & 3;
    const int wn   = warp >> 2;
    const int row0 = blockIdx.x * 128;

    float acc[2][4][4];
#pragma unroll
    for (int mi = 0; mi < 2; mi++)
#pragma unroll
        for (int ni = 0; ni < 4; ni++)
#pragma unroll
            for (int q = 0; q < 4; q++) acc[mi][ni][q] = 0.f;

    const int ar = tid >> 1, ac = (tid & 1) * 64;
    {
        int gr = row0 + ar;
        bool ok = gr < n;
        const __half* Arow = A + (size_t)gr * 128 + ac;
#pragma unroll
        for (int u = 0; u < 8; u++)
            cp16p(sm_u32(&AS(ar, ac + u * 8)), Arow + u * 8, ok);
    }
    {
        const int wr = tid >> 1, wc = (tid & 1) * 32;   // 128 rows x 64 halves
        const __half* Wrow = g_W2p + wr * 64 + wc;
#pragma unroll
        for (int u = 0; u < 4; u++)
            cp16(sm_u32(&WS40(wr, wc + u * 8)), Wrow + u * 8);
    }
    cp_wait();
    __syncthreads();

#pragma unroll
    for (int kk = 0; kk < 8; kk++) {
        unsigned af[2][4];
#pragma unroll
        for (int mi = 0; mi < 2; mi++) {
            int r = wm * 32 + mi * 16 + (lane & 15);
            int kh = kk * 16 + (lane >> 4) * 8;
            ldm_x4(af[mi], sm_u32(&AS(r, kh)));
        }
        unsigned bf[4][2];
#pragma unroll
        for (int nt = 0; nt < 2; nt++) {
            int g = lane >> 3, r = lane & 7;
            int krow = kk * 16 + (g & 1) * 8 + r;
            int ncol = wn * 32 + nt * 16 + (g >> 1) * 8;
            unsigned t[4];
            ldm_x4t(t, sm_u32(&WS40(krow, ncol)));
            bf[nt * 2 + 0][0] = t[0]; bf[nt * 2 + 0][1] = t[1];
            bf[nt * 2 + 1][0] = t[2]; bf[nt * 2 + 1][1] = t[3];
        }
#pragma unroll
        for (int mi = 0; mi < 2; mi++)
#pragma unroll
            for (int ni = 0; ni < 4; ni++)
                mma16816(acc[mi][ni], af[mi], bf[ni]);
    }

    const int r1 = lane >> 2;
    const int c2 = (lane & 3) * 2;
#pragma unroll
    for (int mi = 0; mi < 2; mi++) {
        int gr0 = row0 + wm * 32 + mi * 16 + r1;
        int gr1 = gr0 + 8;
        float d0 = (gr0 < n) ? g_dinv[gr0] : 0.f;
        float d1 = (gr1 < n) ? g_dinv[gr1] : 0.f;
#pragma unroll
        for (int ni = 0; ni < 4; ni++) {
            int col = wn * 32 + ni * 8 + c2;
            if (col >= 40) continue;
            if (gr0 < n) {
                __half2 h = __floats2half2_rn(acc[mi][ni][0] * d0,
                                              acc[mi][ni][1] * d0);
                *(unsigned*)(H2h + (size_t)gr0 * 40 + col) = *(unsigned*)&h;
            }
            if (gr1 < n) {
                __half2 h = __floats2half2_rn(acc[mi][ni][2] * d1,
                                              acc[mi][ni][3] * d1);
                *(unsigned*)(H2h + (size_t)gr1 * 40 + col) = *(unsigned*)&h;
            }
        }
    }
}

// ------------------------------------------------------------------
// SpMM (fp16 messages; self-loop + bias + RELU folded):
//   AGG[d] = half(relu(dinv[d] * (Hh[d] + sum Hh[s]) + b))
// ------------------------------------------------------------------
__global__ __launch_bounds__(256)
void k_spmm128(const __half* __restrict__ hh, __half* __restrict__ agg,
               const float* __restrict__ b, int n) {
    int w = (blockIdx.x * blockDim.x + threadIdx.x) >> 5;
    if (w >= n) return;
    int lane = threadIdx.x & 31;
    int beg = g_rowptr[w];
    int end = g_rowptr[w + 1];
    float dd = g_dinv[w];
    uint2 us = *(const uint2*)(hh + (size_t)w * 128 + lane * 4);
    float2 s0 = __half22float2(*(const __half2*)&us.x);
    float2 s1 = __half22float2(*(const __half2*)&us.y);
    float4 acc = make_float4(s0.x, s0.y, s1.x, s1.y);

    int idx = beg;
    for (; idx + 4 <= end; idx += 4) {
        int i0 = g_csr[idx + 0], i1 = g_csr[idx + 1];
        int i2 = g_csr[idx + 2], i3 = g_csr[idx + 3];
        uint2 u0 = *(const uint2*)(hh + (size_t)i0 * 128 + lane * 4);
        uint2 u1 = *(const uint2*)(hh + (size_t)i1 * 128 + lane * 4);
        uint2 u2 = *(const uint2*)(hh + (size_t)i2 * 128 + lane * 4);
        uint2 u3 = *(const uint2*)(hh + (size_t)i3 * 128 + lane * 4);
#pragma unroll
        for (int q = 0; q < 4; q++) {
            uint2 u = (q == 0) ? u0 : (q == 1) ? u1 : (q == 2) ? u2 : u3;
            float2 f0 = __half22float2(*(const __half2*)&u.x);
            float2 f1 = __half22float2(*(const __half2*)&u.y);
            acc.x += f0.x; acc.y += f0.y; acc.z += f1.x; acc.w += f1.y;
        }
    }
    for (; idx < end; ++idx) {
        int s = g_csr[idx];
        uint2 u = *(const uint2*)(hh + (size_t)s * 128 + lane * 4);
        float2 f0 = __half22float2(*(const __half2*)&u.x);
        float2 f1 = __half22float2(*(const __half2*)&u.y);
        acc.x += f0.x; acc.y += f0.y; acc.z += f1.x; acc.w += f1.y;
    }
    float4 bv = *(const float4*)(b + lane * 4);
    float rx = fmaxf(dd * acc.x + bv.x, 0.f);
    float ry = fmaxf(dd * acc.y + bv.y, 0.f);
    float rz = fmaxf(dd * acc.z + bv.z, 0.f);
    float rw = fmaxf(dd * acc.w + bv.w, 0.f);
    __half2 r0 = __floats2half2_rn(rx, ry);
    __half2 r1 = __floats2half2_rn(rz, rw);
    uint2 res; res.x = *(unsigned*)&r0; res.y = *(unsigned*)&r1;
    *(uint2*)(agg + (size_t)w * 128 + lane * 4) = res;
}

// layer-2 final: OUT[d] = dinv[d] * (H2h[d] + sum H2h[s]) + b2 (fp32, no relu)
__global__ __launch_bounds__(256)
void k_spmm40h(const __half* __restrict__ hh, float* __restrict__ out,
               const float* __restrict__ b, int n) {
    int w = (blockIdx.x * blockDim.x + threadIdx.x) >> 5;
    if (w >= n) return;
    int lane = threadIdx.x & 31;
    if (lane >= 20) return;
    int beg = g_rowptr[w];
    int end = g_rowptr[w + 1];
    float dd = g_dinv[w];
    unsigned usf = *(const unsigned*)(hh + (size_t)w * 40 + lane * 2);
    float2 acc = __half22float2(*(const __half2*)&usf);

    int idx = beg;
    for (; idx + 4 <= end; idx += 4) {
        int i0 = g_csr[idx + 0], i1 = g_csr[idx + 1];
        int i2 = g_csr[idx + 2], i3 = g_csr[idx + 3];
        unsigned u0 = *(const unsigned*)(hh + (size_t)i0 * 40 + lane * 2);
        unsigned u1 = *(const unsigned*)(hh + (size_t)i1 * 40 + lane * 2);
        unsigned u2 = *(const unsigned*)(hh + (size_t)i2 * 40 + lane * 2);
        unsigned u3 = *(const unsigned*)(hh + (size_t)i3 * 40 + lane * 2);
        float2 f0 = __half22float2(*(const __half2*)&u0);
        float2 f1 = __half22float2(*(const __half2*)&u1);
        float2 f2 = __half22float2(*(const __half2*)&u2);
        float2 f3 = __half22float2(*(const __half2*)&u3);
        acc.x += f0.x + f1.x + f2.x + f3.x;
        acc.y += f0.y + f1.y + f2.y + f3.y;
    }
    for (; idx < end; ++idx) {
        int s = g_csr[idx];
        unsigned u = *(const unsigned*)(hh + (size_t)s * 40 + lane * 2);
        float2 f = __half22float2(*(const __half2*)&u);
        acc.x += f.x; acc.y += f.y;
    }
    float2 bv = *(const float2*)(b + lane * 2);
    float2 res = make_float2(dd * acc.x + bv.x, dd * acc.y + bv.y);
    *(float2*)(out + (size_t)w * 40 + lane * 2) = res;
}

// ------------------------------------------------------------------
extern "C" void kernel_launch(void* const* d_in, const int* in_sizes, int n_in,
                              void* d_out, int out_size) {
    const float* x  = (const float*)d_in[0];
    const float* W0 = (const float*)d_in[1];
    const float* b0 = (const float*)d_in[2];
    const float* W1 = (const float*)d_in[3];
    const float* b1 = (const float*)d_in[4];
    const float* W2 = (const float*)d_in[5];
    const float* b2 = (const float*)d_in[6];
    const void*  ei = d_in[7];
    int n = in_sizes[0] / FEAT;
    int E = in_sizes[7] / 2;
    if (E > EMAX) E = EMAX;
    float* out = (float*)d_out;

    __half *pHh, *pH2h, *pAGG, *pW0h, *pW1h;
    cudaGetSymbolAddress((void**)&pHh,  g_Hh);
    cudaGetSymbolAddress((void**)&pH2h, g_H2h);
    cudaGetSymbolAddress((void**)&pAGG, g_AGG);
    cudaGetSymbolAddress((void**)&pW0h, g_W0h);
    cudaGetSymbolAddress((void**)&pW1h, g_W1h);

    static cudaStream_t s2 = nullptr;
    static cudaEvent_t evFork = nullptr, evJoin = nullptr;
    static bool attrSet = false;
    if (!s2) {
        cudaStreamCreateWithFlags(&s2, cudaStreamNonBlocking);
        cudaEventCreateWithFlags(&evFork, cudaEventDisableTiming);
        cudaEventCreateWithFlags(&evJoin, cudaEventDisableTiming);
    }
    const int GSMEM  = 2 * 17408 * (int)sizeof(__half);          // 69632 B
    const int GSMEM40 = (17408 + 128 * 72) * (int)sizeof(__half); // 53248 B
    if (!attrSet) {
        cudaFuncSetAttribute(k_gemm128h<false>,
                             cudaFuncAttributeMaxDynamicSharedMemorySize, GSMEM);
        cudaFuncSetAttribute(k_gemm128h<true>,
                             cudaFuncAttributeMaxDynamicSharedMemorySize, GSMEM);
        cudaFuncSetAttribute(k_gemm40h,
                             cudaFuncAttributeMaxDynamicSharedMemorySize, GSMEM40);
        attrSet = true;
    }

    const int tb = 256;
    int nblk  = (n + tb - 1) / tb;
    int eblk  = (E + tb - 1) / tb;
    int gblk  = (n + 127) / 128;
    int scblk = (n + 1023) / 1024;
    int wblk  = (int)(((long long)n * 32 + tb - 1) / tb);

    // ---- degree + dinv + weight conversion ----
    k_zero_deg<<<nblk, tb>>>(ei, n);
    k_count<<<eblk, tb>>>(ei, E);
    k_scanA<<<scblk, 1024>>>(n);
    k_convW<<<(40960 + tb - 1) / tb, tb>>>(W0, W1, W2);

    // ---- fork: layer-0 GEMM on s2 || CSR finish on main ----
    cudaEventRecord(evFork, 0);
    cudaStreamWaitEvent(s2, evFork, 0);
    k_gemm128h<false><<<gblk, 256, GSMEM, s2>>>(x, pW0h, pHh, n);
    cudaEventRecord(evJoin, s2);

    k_scanB<<<1, 128>>>(scblk);
    k_scanC<<<scblk, 1024>>>(n, E);
    k_fill<<<eblk, tb>>>(ei, E);
    cudaStreamWaitEvent(0, evJoin, 0);

    // ---- pipeline ----
    k_spmm128<<<wblk, tb>>>(pHh, pAGG, b0, n);
    k_gemm128h<true><<<gblk, 256, GSMEM>>>(pAGG, pW1h, pHh, n);
    k_spmm128<<<wblk, tb>>>(pHh, pAGG, b1, n);
    k_gemm40h<<<gblk, 256, GSMEM40>>>(pAGG, pH2h, n);
    k_spmm40h<<<wblk, tb>>>(pH2h, out, b2, n);
}